// round 5
// baseline (speedup 1.0000x reference)
#include <cuda_runtime.h>
#include <math.h>
#include <stdint.h>

#define L 512
#define LL (L*L)
#define PZ 136   // pitch for k-interleaved tf32 tiles (mod 32 == 8 words)
#define PS 40    // syrk chunk pitch (mod 32 == 8 words)

// ---- scratch (device globals; allocation-free contract) ----
__device__ float    g_gate[(size_t)LL*128];
__device__ uint32_t g_at  [(size_t)128*LL]; // gated a, tf32 bits, l-dim k-permuted
__device__ float    g_o   [(size_t)128*LL];
__device__ uint32_t g_awt [128*128];        // tf32 weights, k-permuted
__device__ uint32_t g_agwt[128*128];
__device__ uint32_t g_gwt [128*128];
__device__ uint32_t g_owt [128*128];

__device__ __forceinline__ float sigmoidf_(float x) { return 1.0f / (1.0f + expf(-x)); }

__device__ __forceinline__ uint32_t f2tf(float f) {
    uint32_t u;
    asm("cvt.rna.tf32.f32 %0, %1;" : "=r"(u) : "f"(f));
    return u;
}

// permute k within 8-group: o -> (o&3)*2 + (o>>2)   (order 0,4,1,5,2,6,3,7)
__device__ __forceinline__ int kperm(int k) {
    return (k & ~7) | (((k & 3) << 1) | ((k >> 2) & 1));
}

__device__ __forceinline__ void mma8(float* c, const uint32_t* a, uint32_t b0, uint32_t b1) {
    asm volatile(
        "mma.sync.aligned.m16n8k8.row.col.f32.tf32.tf32.f32 "
        "{%0,%1,%2,%3}, {%4,%5,%6,%7}, {%8,%9}, {%0,%1,%2,%3};\n"
        : "+f"(c[0]), "+f"(c[1]), "+f"(c[2]), "+f"(c[3])
        : "r"(a[0]), "r"(a[1]), "r"(a[2]), "r"(a[3]), "r"(b0), "r"(b1));
}

__device__ __forceinline__ void cpa16(void* dst, const void* src) {
    uint32_t s = (uint32_t)__cvta_generic_to_shared(dst);
    asm volatile("cp.async.cg.shared.global [%0], [%1], 16;\n" :: "r"(s), "l"(src));
}
__device__ __forceinline__ void cpa_commit() { asm volatile("cp.async.commit_group;\n" ::: "memory"); }
template<int N> __device__ __forceinline__ void cpa_wait() {
    asm volatile("cp.async.wait_group %0;\n" :: "n"(N) : "memory");
}

// ============================================================
// K0: pre-convert weights to tf32 bits, k-permuted within rows
// ============================================================
__global__ void prep_w(const float* __restrict__ aw, const float* __restrict__ agw,
                       const float* __restrict__ gw, const float* __restrict__ ow) {
    int idx = blockIdx.x * 512 + threadIdx.x;   // 65536 total
    int w = idx >> 14, i = idx & 16383;
    int d = kperm(i);   // row stride 128 keeps low 3 bits = k&7
    if (w == 0)      g_awt [d] = f2tf(aw[i]);
    else if (w == 1) g_agwt[d] = f2tf(agw[i]);
    else if (w == 2) g_gwt [d] = f2tf(gw[i]);
    else             g_owt [d] = f2tf(ow[i]);
}

// ============================================================
// K1: fused LN + dual GEMM (a,ag) + gating + permuted transposed
//     tf32 write of a + gate GEMM. 512 thr, 4x4 warps, 32x32 tile.
// ============================================================
__global__ void __launch_bounds__(512, 1)
fusedA(const float* __restrict__ z, const float* __restrict__ ng, const float* __restrict__ nb,
       const float* __restrict__ ab, const float* __restrict__ agb, const float* __restrict__ gb) {
    extern __shared__ uint32_t sm[];
    uint32_t* sZ  = sm;               // 128*PZ tf32 zn (k-permuted)
    uint32_t* sWa = sm + 128 * PZ;    // a_w, later g_w
    uint32_t* sWb = sm + 2 * 128 * PZ;// ag_w, later P staging
    const int tid = threadIdx.x;
    const int wid = tid >> 5, lane = tid & 31;
    const int wm = wid >> 2, wn = wid & 3;
    const int lr = lane >> 2, lc = lane & 3;
    const size_t m0 = (size_t)blockIdx.x * 128;

    // async weight loads (already permuted in gmem)
#pragma unroll
    for (int e = 0; e < 8; e++) {
        int idx = tid + 512 * e;
        int r = idx >> 5, c4 = idx & 31;
        cpa16(sWa + r * PZ + c4 * 4, g_awt  + r * 128 + c4 * 4);
        cpa16(sWb + r * PZ + c4 * 4, g_agwt + r * 128 + c4 * 4);
    }
    cpa_commit();

    // LayerNorm: warp w handles rows [8w, 8w+8); write k-permuted
    float4 g4 = reinterpret_cast<const float4*>(ng)[lane];
    float4 b4 = reinterpret_cast<const float4*>(nb)[lane];
    const int sgrp = (lane >> 1) * 8 + (lane & 1);
    for (int it = 0; it < 8; it++) {
        int row = wid * 8 + it;
        float4 v = reinterpret_cast<const float4*>(z)[(m0 + row) * 32 + lane];
        float s = v.x + v.y + v.z + v.w;
        float q = v.x*v.x + v.y*v.y + v.z*v.z + v.w*v.w;
#pragma unroll
        for (int o = 16; o > 0; o >>= 1) {
            s += __shfl_xor_sync(0xffffffffu, s, o);
            q += __shfl_xor_sync(0xffffffffu, q, o);
        }
        float mean = s * (1.0f / 128.0f);
        float var  = q * (1.0f / 128.0f) - mean * mean;
        float rs   = rsqrtf(var + 1e-5f);
        uint32_t* d = sZ + row * PZ + sgrp;
        d[0] = f2tf((v.x - mean) * rs * g4.x + b4.x);
        d[2] = f2tf((v.y - mean) * rs * g4.y + b4.y);
        d[4] = f2tf((v.z - mean) * rs * g4.z + b4.z);
        d[6] = f2tf((v.w - mean) * rs * g4.w + b4.w);
    }
    cpa_wait<0>();
    __syncthreads();

    // ---- pass 1: dual GEMM (a_w and ag_w share A fragments) ----
    float acc_a[2][4][4], acc_q[2][4][4];
#pragma unroll
    for (int mf = 0; mf < 2; mf++)
#pragma unroll
        for (int nf = 0; nf < 4; nf++)
#pragma unroll
            for (int v = 0; v < 4; v++) { acc_a[mf][nf][v] = 0.0f; acc_q[mf][nf][v] = 0.0f; }

#pragma unroll
    for (int ks = 0; ks < 16; ks++) {
        int kb = ks * 8;
        uint32_t a[2][4];
#pragma unroll
        for (int mf = 0; mf < 2; mf++) {
            int row = wm * 32 + mf * 16 + lr;
            uint2 lo = *reinterpret_cast<const uint2*>(sZ + row * PZ + kb + 2 * lc);
            uint2 hi = *reinterpret_cast<const uint2*>(sZ + (row + 8) * PZ + kb + 2 * lc);
            a[mf][0] = lo.x; a[mf][1] = hi.x; a[mf][2] = lo.y; a[mf][3] = hi.y;
        }
#pragma unroll
        for (int nf = 0; nf < 4; nf++) {
            int col = wn * 32 + nf * 8 + lr;
            uint2 ba = *reinterpret_cast<const uint2*>(sWa + col * PZ + kb + 2 * lc);
            uint2 bq = *reinterpret_cast<const uint2*>(sWb + col * PZ + kb + 2 * lc);
            mma8(acc_a[0][nf], a[0], ba.x, ba.y);
            mma8(acc_a[1][nf], a[1], ba.x, ba.y);
            mma8(acc_q[0][nf], a[0], bq.x, bq.y);
            mma8(acc_q[1][nf], a[1], bq.x, bq.y);
        }
    }
    __syncthreads();

    // prefetch g_w into sWa
#pragma unroll
    for (int e = 0; e < 8; e++) {
        int idx = tid + 512 * e;
        int r = idx >> 5, c4 = idx & 31;
        cpa16(sWa + r * PZ + c4 * 4, g_gwt + r * 128 + c4 * 4);
    }
    cpa_commit();

    // epilogue pass 1: P = (a + ab) * sigmoid(q + agb), staged transposed in sWb
    float* sP = reinterpret_cast<float*>(sWb);
#pragma unroll
    for (int mf = 0; mf < 2; mf++) {
#pragma unroll
        for (int nf = 0; nf < 4; nf++) {
            int rowl = wm * 32 + mf * 16 + lr;
            int col  = wn * 32 + nf * 8 + 2 * lc;
            float ba0 = __ldg(ab + col),  ba1 = __ldg(ab + col + 1);
            float bq0 = __ldg(agb + col), bq1 = __ldg(agb + col + 1);
            sP[col * PZ + rowl]          = (acc_a[mf][nf][0] + ba0) * sigmoidf_(acc_q[mf][nf][0] + bq0);
            sP[(col + 1) * PZ + rowl]    = (acc_a[mf][nf][1] + ba1) * sigmoidf_(acc_q[mf][nf][1] + bq1);
            sP[col * PZ + rowl + 8]      = (acc_a[mf][nf][2] + ba0) * sigmoidf_(acc_q[mf][nf][2] + bq0);
            sP[(col + 1) * PZ + rowl + 8]= (acc_a[mf][nf][3] + ba1) * sigmoidf_(acc_q[mf][nf][3] + bq1);
        }
    }
    __syncthreads();

    // write a transposed (l-dim k-permuted) as tf32 bits
#pragma unroll 8
    for (int e = 0; e < 32; e++) {
        int idx = tid + 512 * e;
        int r = idx & 127, c = idx >> 7;
        g_at[(size_t)c * LL + m0 + kperm(r)] = f2tf(sP[c * PZ + r]);
    }
    cpa_wait<0>();
    __syncthreads();

    // ---- pass 2: gate GEMM ----
#pragma unroll
    for (int mf = 0; mf < 2; mf++)
#pragma unroll
        for (int nf = 0; nf < 4; nf++)
#pragma unroll
            for (int v = 0; v < 4; v++) acc_a[mf][nf][v] = 0.0f;

#pragma unroll
    for (int ks = 0; ks < 16; ks++) {
        int kb = ks * 8;
        uint32_t a[2][4];
#pragma unroll
        for (int mf = 0; mf < 2; mf++) {
            int row = wm * 32 + mf * 16 + lr;
            uint2 lo = *reinterpret_cast<const uint2*>(sZ + row * PZ + kb + 2 * lc);
            uint2 hi = *reinterpret_cast<const uint2*>(sZ + (row + 8) * PZ + kb + 2 * lc);
            a[mf][0] = lo.x; a[mf][1] = hi.x; a[mf][2] = lo.y; a[mf][3] = hi.y;
        }
#pragma unroll
        for (int nf = 0; nf < 4; nf++) {
            int col = wn * 32 + nf * 8 + lr;
            uint2 bg = *reinterpret_cast<const uint2*>(sWa + col * PZ + kb + 2 * lc);
            mma8(acc_a[0][nf], a[0], bg.x, bg.y);
            mma8(acc_a[1][nf], a[1], bg.x, bg.y);
        }
    }

#pragma unroll
    for (int mf = 0; mf < 2; mf++) {
#pragma unroll
        for (int nf = 0; nf < 4; nf++) {
            size_t row = m0 + wm * 32 + mf * 16 + lr;
            int col = wn * 32 + nf * 8 + 2 * lc;
            float b0v = __ldg(gb + col), b1v = __ldg(gb + col + 1);
            *reinterpret_cast<float2*>(g_gate + row * 128 + col) =
                make_float2(sigmoidf_(acc_a[mf][nf][0] + b0v), sigmoidf_(acc_a[mf][nf][1] + b1v));
            *reinterpret_cast<float2*>(g_gate + (row + 8) * 128 + col) =
                make_float2(sigmoidf_(acc_a[mf][nf][2] + b0v), sigmoidf_(acc_a[mf][nf][3] + b1v));
        }
    }
}

// ============================================================
// K2: tf32 SYRK per channel, cp.async double-buffered. 256 thr.
//     g_at already k-permuted in l-dim -> vector frag loads.
// ============================================================
__global__ void __launch_bounds__(256, 2)
syrk_mma() {
    extern __shared__ uint32_t sm[];   // 2 stages x (A + B), pitch PS
    const int tid  = threadIdx.x;
    const int wid  = tid >> 5, lane = tid & 31;
    const int wm   = wid >> 1, wn = wid & 1;
    const int lr   = lane >> 2, lc = lane & 3;

    const int c = blockIdx.y;
    int rem = blockIdx.x, bi = 0, span = 4;
    while (rem >= span) { rem -= span; span--; bi++; }
    int bj = bi + rem;
    const int i0 = bi * 128, j0 = bj * 128;
    const bool diag = (bi == bj);

    const uint32_t* __restrict__ Ag = g_at + (size_t)c * LL;
    float* __restrict__ O = g_o + (size_t)c * LL;

    const int STG_SZ = 2 * 128 * PS;   // words per stage (A+B)

    auto load_chunk = [&](int kc, int buf) {
        uint32_t* sA = sm + buf * STG_SZ;
        uint32_t* sB = sA + 128 * PS;
#pragma unroll
        for (int e = 0; e < 4; e++) {
            int idx = tid + 256 * e;   // 1024 uint4
            int r = idx >> 3, c4 = idx & 7;
            cpa16(sA + r * PS + c4 * 4, Ag + (size_t)(i0 + r) * 512 + kc * 32 + c4 * 4);
            if (!diag)
                cpa16(sB + r * PS + c4 * 4, Ag + (size_t)(j0 + r) * 512 + kc * 32 + c4 * 4);
        }
        cpa_commit();
    };

    float acc[2][8][4];
#pragma unroll
    for (int mf = 0; mf < 2; mf++)
#pragma unroll
        for (int nf = 0; nf < 8; nf++)
#pragma unroll
            for (int v = 0; v < 4; v++) acc[mf][nf][v] = 0.0f;

    load_chunk(0, 0);

    for (int kc = 0; kc < 16; kc++) {
        if (kc + 1 < 16) { load_chunk(kc + 1, (kc + 1) & 1); cpa_wait<1>(); }
        else             { cpa_wait<0>(); }
        __syncthreads();
        const uint32_t* sA = sm + (kc & 1) * STG_SZ;
        const uint32_t* sB = diag ? sA : sA + 128 * PS;
#pragma unroll
        for (int ks = 0; ks < 4; ks++) {
            int kb = ks * 8;
            uint32_t a[2][4];
#pragma unroll
            for (int mf = 0; mf < 2; mf++) {
                int row = wm * 32 + mf * 16 + lr;
                uint2 lo = *reinterpret_cast<const uint2*>(sA + row * PS + kb + 2 * lc);
                uint2 hi = *reinterpret_cast<const uint2*>(sA + (row + 8) * PS + kb + 2 * lc);
                a[mf][0] = lo.x; a[mf][1] = hi.x; a[mf][2] = lo.y; a[mf][3] = hi.y;
            }
#pragma unroll
            for (int nf = 0; nf < 8; nf++) {
                int col = wn * 64 + nf * 8 + lr;
                uint2 b = *reinterpret_cast<const uint2*>(sB + col * PS + kb + 2 * lc);
                mma8(acc[0][nf], a[0], b.x, b.y);
                mma8(acc[1][nf], a[1], b.x, b.y);
            }
        }
        __syncthreads();
    }

    // direct tile write
#pragma unroll
    for (int mf = 0; mf < 2; mf++) {
#pragma unroll
        for (int nf = 0; nf < 8; nf++) {
            int rowi = i0 + wm * 32 + mf * 16 + lr;
            int colj = j0 + wn * 64 + nf * 8 + 2 * lc;
            *reinterpret_cast<float2*>(O + (size_t)rowi * 512 + colj) =
                make_float2(acc[mf][nf][0], acc[mf][nf][1]);
            *reinterpret_cast<float2*>(O + (size_t)(rowi + 8) * 512 + colj) =
                make_float2(acc[mf][nf][2], acc[mf][nf][3]);
        }
    }

    // mirror via smem transpose staging
    if (!diag) {
        float* st = reinterpret_cast<float*>(sm);
#pragma unroll
        for (int sblk = 0; sblk < 4; sblk++) {
            __syncthreads();
            if (wm == sblk) {
#pragma unroll
                for (int mf = 0; mf < 2; mf++)
#pragma unroll
                    for (int nf = 0; nf < 8; nf++) {
                        int rl = mf * 16 + lr;
                        int col = wn * 64 + nf * 8 + 2 * lc;
                        st[rl * 132 + col]           = acc[mf][nf][0];
                        st[rl * 132 + col + 1]       = acc[mf][nf][1];
                        st[(rl + 8) * 132 + col]     = acc[mf][nf][2];
                        st[(rl + 8) * 132 + col + 1] = acc[mf][nf][3];
                    }
            }
            __syncthreads();
#pragma unroll 4
            for (int idx = tid; idx < 128 * 32; idx += 256) {
                int nn = idx >> 5, rl = idx & 31;
                O[(size_t)(j0 + nn) * 512 + i0 + sblk * 32 + rl] = st[rl * 132 + nn];
            }
        }
    }
}

// ============================================================
// K3: fused gather + channel-LN + final projection + gating.
//     512 thr, 4x4 warps. B-frags vectorized (permuted o_w).
// ============================================================
__global__ void __launch_bounds__(512, 1)
fusedC(const float* __restrict__ ong, const float* __restrict__ onb,
       const float* __restrict__ ob, float* __restrict__ out) {
    extern __shared__ uint32_t sm[];
    float*    sO = reinterpret_cast<float*>(sm);   // [c][jj], pitch 132
    uint32_t* sW = sm + 128 * 132;                 // o_w, pitch PZ, permuted
    __shared__ float ps[4][128], pq[4][128], mS[128], rS[128];

    const int tid = threadIdx.x;
    const int wid = tid >> 5, lane = tid & 31;
    const int wm = wid >> 2, wn = wid & 3;
    const int lr = lane >> 2, lc = lane & 3;
    const int i = blockIdx.y, j0 = blockIdx.x * 128;

#pragma unroll
    for (int e = 0; e < 8; e++) {
        int idx = tid + 512 * e;
        int r = idx >> 5, c4 = idx & 31;
        cpa16(sW + r * PZ + c4 * 4, g_owt + r * 128 + c4 * 4);
    }
    cpa_commit();

    // gather o tile [c][jj]
#pragma unroll
    for (int e = 0; e < 8; e++) {
        int idx = tid + 512 * e;
        int c = idx >> 5, j4 = idx & 31;
        float4 v = reinterpret_cast<const float4*>(g_o + (size_t)c * LL + (size_t)i * 512 + j0)[j4];
        *reinterpret_cast<float4*>(sO + c * 132 + j4 * 4) = v;
    }
    __syncthreads();

    // channel reduce
    {
        int col = tid & 127, qtr = tid >> 7;
        float s = 0.0f, q = 0.0f;
#pragma unroll 8
        for (int c = qtr * 32; c < qtr * 32 + 32; c++) {
            float v = sO[c * 132 + col];
            s += v; q += v * v;
        }
        ps[qtr][col] = s; pq[qtr][col] = q;
    }
    __syncthreads();
    if (tid < 128) {
        float ss = ps[0][tid] + ps[1][tid] + ps[2][tid] + ps[3][tid];
        float qq = pq[0][tid] + pq[1][tid] + pq[2][tid] + pq[3][tid];
        float mean = ss * (1.0f / 128.0f);
        float var  = qq * (1.0f / 128.0f) - mean * mean;
        mS[tid] = mean;
        rS[tid] = rsqrtf(var + 1e-5f);
    }
    __syncthreads();

    // normalize in place -> tf32 bits
#pragma unroll 8
    for (int e = 0; e < 32; e++) {
        int idx = tid + 512 * e;
        int jj = idx & 127, c = idx >> 7;
        float v = (sO[c * 132 + jj] - mS[jj]) * rS[jj] * __ldg(ong + c) + __ldg(onb + c);
        sm[c * 132 + jj] = f2tf(v);
    }
    __syncthreads();

    // GEMM: rows = jj, K = c. A scalar (K slow dim), B vectorized.
    float acc[2][4][4];
#pragma unroll
    for (int mf = 0; mf < 2; mf++)
#pragma unroll
        for (int nf = 0; nf < 4; nf++)
#pragma unroll
            for (int v = 0; v < 4; v++) acc[mf][nf][v] = 0.0f;

#pragma unroll
    for (int ks = 0; ks < 16; ks++) {
        int kb = ks * 8;
        uint32_t a[2][4];
#pragma unroll
        for (int mf = 0; mf < 2; mf++) {
            int row = wm * 32 + mf * 16 + lr;
            a[mf][0] = sm[(kb + lc) * 132 + row];
            a[mf][1] = sm[(kb + lc) * 132 + row + 8];
            a[mf][2] = sm[(kb + 4 + lc) * 132 + row];
            a[mf][3] = sm[(kb + 4 + lc) * 132 + row + 8];
        }
#pragma unroll
        for (int nf = 0; nf < 4; nf++) {
            int col = wn * 32 + nf * 8 + lr;
            uint2 b = *reinterpret_cast<const uint2*>(sW + col * PZ + kb + 2 * lc);
            mma8(acc[0][nf], a[0], b.x, b.y);
            mma8(acc[1][nf], a[1], b.x, b.y);
        }
    }

    const size_t grow = (size_t)i * 512 + j0;
#pragma unroll
    for (int mf = 0; mf < 2; mf++) {
#pragma unroll
        for (int nf = 0; nf < 4; nf++) {
            size_t row = grow + wm * 32 + mf * 16 + lr;
            int col = wn * 32 + nf * 8 + 2 * lc;
            float b0v = __ldg(ob + col), b1v = __ldg(ob + col + 1);
            float2 gt0 = *reinterpret_cast<const float2*>(g_gate + row * 128 + col);
            float2 gt1 = *reinterpret_cast<const float2*>(g_gate + (row + 8) * 128 + col);
            *reinterpret_cast<float2*>(out + row * 128 + col) =
                make_float2((acc[mf][nf][0] + b0v) * gt0.x, (acc[mf][nf][1] + b1v) * gt0.y);
            *reinterpret_cast<float2*>(out + (row + 8) * 128 + col) =
                make_float2((acc[mf][nf][2] + b0v) * gt1.x, (acc[mf][nf][3] + b1v) * gt1.y);
        }
    }
}

// ============================================================
// launch
// ============================================================
extern "C" void kernel_launch(void* const* d_in, const int* in_sizes, int n_in,
                              void* d_out, int out_size) {
    const float* z      = (const float*)d_in[0];
    const float* norm_g = (const float*)d_in[1];
    const float* norm_b = (const float*)d_in[2];
    const float* a_w    = (const float*)d_in[3];
    const float* a_b    = (const float*)d_in[4];
    const float* ag_w   = (const float*)d_in[5];
    const float* ag_b   = (const float*)d_in[6];
    const float* onorm_g= (const float*)d_in[7];
    const float* onorm_b= (const float*)d_in[8];
    const float* o_w    = (const float*)d_in[9];
    const float* o_b    = (const float*)d_in[10];
    const float* g_wp   = (const float*)d_in[11];
    const float* g_bp   = (const float*)d_in[12];
    float* out = (float*)d_out;

    const int SMA = 3 * 128 * PZ * 4;            // 208.9 KB
    const int SMS = 2 * 2 * 128 * PS * 4;        // 81.9 KB
    const int SMC = (128 * 132 + 128 * PZ) * 4;  // 137.2 KB

    static bool attr_done = false;
    if (!attr_done) {
        cudaFuncSetAttribute(fusedA,   cudaFuncAttributeMaxDynamicSharedMemorySize, SMA);
        cudaFuncSetAttribute(syrk_mma, cudaFuncAttributeMaxDynamicSharedMemorySize, SMS);
        cudaFuncSetAttribute(fusedC,   cudaFuncAttributeMaxDynamicSharedMemorySize, SMC);
        attr_done = true;
    }

    prep_w<<<128, 512>>>(a_w, ag_w, g_wp, o_w);
    fusedA<<<LL / 128, 512, SMA>>>(z, norm_g, norm_b, a_b, ag_b, g_bp);
    syrk_mma<<<dim3(10, 128), 256, SMS>>>();
    fusedC<<<dim3(4, L), 512, SMC>>>(onorm_g, onorm_b, o_b, out);
}

// round 6
// speedup vs baseline: 1.1402x; 1.1402x over previous
#include <cuda_runtime.h>
#include <math.h>
#include <stdint.h>

#define L 512
#define LL (L*L)
#define PZ 136   // zn tile pitch (mod 32 == 8 words -> conflict-free uint2 frags)
#define PO 72    // fusedC o-tile pitch (mod 32 == 8)
#define PS 40    // syrk chunk pitch (mod 32 == 8)

// ---- scratch (device globals; allocation-free contract) ----
__device__ float    g_gate[(size_t)LL*128];
__device__ uint32_t g_at  [(size_t)128*LL]; // gated a, tf32 bits, l-dim k-permuted
__device__ float    g_o   [(size_t)128*LL];
__device__ uint32_t g_awt [128*128];        // tf32 weights, k-permuted
__device__ uint32_t g_agwt[128*128];
__device__ uint32_t g_gwt [128*128];
__device__ uint32_t g_owt [128*128];

__device__ __forceinline__ float sigmoidf_(float x) { return 1.0f / (1.0f + expf(-x)); }

__device__ __forceinline__ uint32_t f2tf(float f) {
    uint32_t u;
    asm("cvt.rna.tf32.f32 %0, %1;" : "=r"(u) : "f"(f));
    return u;
}

// permute k within 8-group: order 0,4,1,5,2,6,3,7
__device__ __forceinline__ int kperm(int k) {
    return (k & ~7) | (((k & 3) << 1) | ((k >> 2) & 1));
}

__device__ __forceinline__ void mma8(float* c, const uint32_t* a, uint32_t b0, uint32_t b1) {
    asm volatile(
        "mma.sync.aligned.m16n8k8.row.col.f32.tf32.tf32.f32 "
        "{%0,%1,%2,%3}, {%4,%5,%6,%7}, {%8,%9}, {%0,%1,%2,%3};\n"
        : "+f"(c[0]), "+f"(c[1]), "+f"(c[2]), "+f"(c[3])
        : "r"(a[0]), "r"(a[1]), "r"(a[2]), "r"(a[3]), "r"(b0), "r"(b1));
}

__device__ __forceinline__ void cpa16(void* dst, const void* src) {
    uint32_t s = (uint32_t)__cvta_generic_to_shared(dst);
    asm volatile("cp.async.cg.shared.global [%0], [%1], 16;\n" :: "r"(s), "l"(src));
}
__device__ __forceinline__ void cpa_commit() { asm volatile("cp.async.commit_group;\n" ::: "memory"); }
template<int N> __device__ __forceinline__ void cpa_wait() {
    asm volatile("cp.async.wait_group %0;\n" :: "n"(N) : "memory");
}

// ============================================================
// K0: pre-convert weights to tf32 bits, k-permuted within rows
// ============================================================
__global__ void prep_w(const float* __restrict__ aw, const float* __restrict__ agw,
                       const float* __restrict__ gw, const float* __restrict__ ow) {
    int idx = blockIdx.x * 512 + threadIdx.x;   // 65536 total
    int w = idx >> 14, i = idx & 16383;
    int d = kperm(i);
    if (w == 0)      g_awt [d] = f2tf(aw[i]);
    else if (w == 1) g_agwt[d] = f2tf(agw[i]);
    else if (w == 2) g_gwt [d] = f2tf(gw[i]);
    else             g_owt [d] = f2tf(ow[i]);
}

// ============================================================
// K1: fused LN + dual GEMM (a,ag) + gating + direct permuted
//     transposed store of a + gate GEMM.
//     256 thr, 64-row tile, weights via __ldg (L1), smem = zn only.
//     Warp layout: 8 warps, each owns 16 N-cols x all 64 rows
//     (no duplicate weight reads across warps).
// ============================================================
__global__ void __launch_bounds__(256, 2)
fusedA(const float* __restrict__ z, const float* __restrict__ ng, const float* __restrict__ nb,
       const float* __restrict__ ab, const float* __restrict__ agb, const float* __restrict__ gb) {
    extern __shared__ uint32_t sZ[];   // 64 * PZ tf32 zn (k-permuted)
    const int tid = threadIdx.x;
    const int wid = tid >> 5, lane = tid & 31;
    const int lr = lane >> 2, lc = lane & 3;
    const size_t m0 = (size_t)blockIdx.x * 64;

    // LayerNorm: warp w handles rows [8w, 8w+8); write k-permuted
    {
        float4 g4 = reinterpret_cast<const float4*>(ng)[lane];
        float4 b4 = reinterpret_cast<const float4*>(nb)[lane];
        const int sgrp = (lane >> 1) * 8 + (lane & 1);
#pragma unroll
        for (int it = 0; it < 8; it++) {
            int row = wid * 8 + it;
            float4 v = reinterpret_cast<const float4*>(z)[(m0 + row) * 32 + lane];
            float s = v.x + v.y + v.z + v.w;
            float q = v.x*v.x + v.y*v.y + v.z*v.z + v.w*v.w;
#pragma unroll
            for (int o = 16; o > 0; o >>= 1) {
                s += __shfl_xor_sync(0xffffffffu, s, o);
                q += __shfl_xor_sync(0xffffffffu, q, o);
            }
            float mean = s * (1.0f / 128.0f);
            float var  = q * (1.0f / 128.0f) - mean * mean;
            float rs   = rsqrtf(var + 1e-5f);
            uint32_t* d = sZ + row * PZ + sgrp;
            d[0] = f2tf((v.x - mean) * rs * g4.x + b4.x);
            d[2] = f2tf((v.y - mean) * rs * g4.y + b4.y);
            d[4] = f2tf((v.z - mean) * rs * g4.z + b4.z);
            d[6] = f2tf((v.w - mean) * rs * g4.w + b4.w);
        }
    }
    __syncthreads();

    // ---- dual GEMM: acc_a = zn@a_w^T, acc_q = zn@ag_w^T ----
    float acc_a[4][2][4], acc_q[4][2][4];
#pragma unroll
    for (int mf = 0; mf < 4; mf++)
#pragma unroll
        for (int nf = 0; nf < 2; nf++)
#pragma unroll
            for (int v = 0; v < 4; v++) { acc_a[mf][nf][v] = 0.0f; acc_q[mf][nf][v] = 0.0f; }

#pragma unroll
    for (int ks = 0; ks < 16; ks++) {
        int kb = ks * 8;
        uint32_t a[4][4];
#pragma unroll
        for (int mf = 0; mf < 4; mf++) {
            int row = mf * 16 + lr;
            uint2 lo = *reinterpret_cast<const uint2*>(sZ + row * PZ + kb + 2 * lc);
            uint2 hi = *reinterpret_cast<const uint2*>(sZ + (row + 8) * PZ + kb + 2 * lc);
            a[mf][0] = lo.x; a[mf][1] = hi.x; a[mf][2] = lo.y; a[mf][3] = hi.y;
        }
#pragma unroll
        for (int nf = 0; nf < 2; nf++) {
            int col = wid * 16 + nf * 8 + lr;
            uint2 ba = __ldg(reinterpret_cast<const uint2*>(g_awt  + col * 128 + kb + 2 * lc));
            uint2 bq = __ldg(reinterpret_cast<const uint2*>(g_agwt + col * 128 + kb + 2 * lc));
#pragma unroll
            for (int mf = 0; mf < 4; mf++) {
                mma8(acc_a[mf][nf], a[mf], ba.x, ba.y);
                mma8(acc_q[mf][nf], a[mf], bq.x, bq.y);
            }
        }
    }

    // epilogue: P = (a + ab) * sigmoid(q + agb) -> tf32 -> g_at (direct, sectored)
#pragma unroll
    for (int nf = 0; nf < 2; nf++) {
        int col = wid * 16 + nf * 8 + 2 * lc;
        float ba0 = __ldg(ab + col),  ba1 = __ldg(ab + col + 1);
        float bq0 = __ldg(agb + col), bq1 = __ldg(agb + col + 1);
        const size_t c0 = (size_t)col * LL + m0;
        const size_t c1 = (size_t)(col + 1) * LL + m0;
#pragma unroll
        for (int mf = 0; mf < 4; mf++) {
            int r0 = kperm(mf * 16 + lr), r1 = kperm(mf * 16 + 8 + lr);
            g_at[c0 + r0] = f2tf((acc_a[mf][nf][0] + ba0) * sigmoidf_(acc_q[mf][nf][0] + bq0));
            g_at[c1 + r0] = f2tf((acc_a[mf][nf][1] + ba1) * sigmoidf_(acc_q[mf][nf][1] + bq1));
            g_at[c0 + r1] = f2tf((acc_a[mf][nf][2] + ba0) * sigmoidf_(acc_q[mf][nf][2] + bq0));
            g_at[c1 + r1] = f2tf((acc_a[mf][nf][3] + ba1) * sigmoidf_(acc_q[mf][nf][3] + bq1));
        }
    }

    // ---- gate GEMM (sZ unmodified; no sync needed) ----
    float acc_g[4][2][4];
#pragma unroll
    for (int mf = 0; mf < 4; mf++)
#pragma unroll
        for (int nf = 0; nf < 2; nf++)
#pragma unroll
            for (int v = 0; v < 4; v++) acc_g[mf][nf][v] = 0.0f;

#pragma unroll
    for (int ks = 0; ks < 16; ks++) {
        int kb = ks * 8;
        uint32_t a[4][4];
#pragma unroll
        for (int mf = 0; mf < 4; mf++) {
            int row = mf * 16 + lr;
            uint2 lo = *reinterpret_cast<const uint2*>(sZ + row * PZ + kb + 2 * lc);
            uint2 hi = *reinterpret_cast<const uint2*>(sZ + (row + 8) * PZ + kb + 2 * lc);
            a[mf][0] = lo.x; a[mf][1] = hi.x; a[mf][2] = lo.y; a[mf][3] = hi.y;
        }
#pragma unroll
        for (int nf = 0; nf < 2; nf++) {
            int col = wid * 16 + nf * 8 + lr;
            uint2 bg = __ldg(reinterpret_cast<const uint2*>(g_gwt + col * 128 + kb + 2 * lc));
#pragma unroll
            for (int mf = 0; mf < 4; mf++)
                mma8(acc_g[mf][nf], a[mf], bg.x, bg.y);
        }
    }

#pragma unroll
    for (int nf = 0; nf < 2; nf++) {
        int col = wid * 16 + nf * 8 + 2 * lc;
        float b0v = __ldg(gb + col), b1v = __ldg(gb + col + 1);
#pragma unroll
        for (int mf = 0; mf < 4; mf++) {
            size_t row = m0 + mf * 16 + lr;
            *reinterpret_cast<float2*>(g_gate + row * 128 + col) =
                make_float2(sigmoidf_(acc_g[mf][nf][0] + b0v), sigmoidf_(acc_g[mf][nf][1] + b1v));
            *reinterpret_cast<float2*>(g_gate + (row + 8) * 128 + col) =
                make_float2(sigmoidf_(acc_g[mf][nf][2] + b0v), sigmoidf_(acc_g[mf][nf][3] + b1v));
        }
    }
}

// ============================================================
// K2: tf32 SYRK per channel, cp.async double-buffered. 256 thr.
// ============================================================
__global__ void __launch_bounds__(256, 2)
syrk_mma() {
    extern __shared__ uint32_t sm[];
    const int tid  = threadIdx.x;
    const int wid  = tid >> 5, lane = tid & 31;
    const int wm   = wid >> 1, wn = wid & 1;
    const int lr   = lane >> 2, lc = lane & 3;

    const int c = blockIdx.y;
    int rem = blockIdx.x, bi = 0, span = 4;
    while (rem >= span) { rem -= span; span--; bi++; }
    int bj = bi + rem;
    const int i0 = bi * 128, j0 = bj * 128;
    const bool diag = (bi == bj);

    const uint32_t* __restrict__ Ag = g_at + (size_t)c * LL;
    float* __restrict__ O = g_o + (size_t)c * LL;

    const int STG_SZ = 2 * 128 * PS;

    auto load_chunk = [&](int kc, int buf) {
        uint32_t* sA = sm + buf * STG_SZ;
        uint32_t* sB = sA + 128 * PS;
#pragma unroll
        for (int e = 0; e < 4; e++) {
            int idx = tid + 256 * e;
            int r = idx >> 3, c4 = idx & 7;
            cpa16(sA + r * PS + c4 * 4, Ag + (size_t)(i0 + r) * 512 + kc * 32 + c4 * 4);
            if (!diag)
                cpa16(sB + r * PS + c4 * 4, Ag + (size_t)(j0 + r) * 512 + kc * 32 + c4 * 4);
        }
        cpa_commit();
    };

    float acc[2][8][4];
#pragma unroll
    for (int mf = 0; mf < 2; mf++)
#pragma unroll
        for (int nf = 0; nf < 8; nf++)
#pragma unroll
            for (int v = 0; v < 4; v++) acc[mf][nf][v] = 0.0f;

    load_chunk(0, 0);

    for (int kc = 0; kc < 16; kc++) {
        if (kc + 1 < 16) { load_chunk(kc + 1, (kc + 1) & 1); cpa_wait<1>(); }
        else             { cpa_wait<0>(); }
        __syncthreads();
        const uint32_t* sA = sm + (kc & 1) * STG_SZ;
        const uint32_t* sB = diag ? sA : sA + 128 * PS;
#pragma unroll
        for (int ks = 0; ks < 4; ks++) {
            int kb = ks * 8;
            uint32_t a[2][4];
#pragma unroll
            for (int mf = 0; mf < 2; mf++) {
                int row = wm * 32 + mf * 16 + lr;
                uint2 lo = *reinterpret_cast<const uint2*>(sA + row * PS + kb + 2 * lc);
                uint2 hi = *reinterpret_cast<const uint2*>(sA + (row + 8) * PS + kb + 2 * lc);
                a[mf][0] = lo.x; a[mf][1] = hi.x; a[mf][2] = lo.y; a[mf][3] = hi.y;
            }
#pragma unroll
            for (int nf = 0; nf < 8; nf++) {
                int col = wn * 64 + nf * 8 + lr;
                uint2 b = *reinterpret_cast<const uint2*>(sB + col * PS + kb + 2 * lc);
                mma8(acc[0][nf], a[0], b.x, b.y);
                mma8(acc[1][nf], a[1], b.x, b.y);
            }
        }
        __syncthreads();
    }

#pragma unroll
    for (int mf = 0; mf < 2; mf++) {
#pragma unroll
        for (int nf = 0; nf < 8; nf++) {
            int rowi = i0 + wm * 32 + mf * 16 + lr;
            int colj = j0 + wn * 64 + nf * 8 + 2 * lc;
            *reinterpret_cast<float2*>(O + (size_t)rowi * 512 + colj) =
                make_float2(acc[mf][nf][0], acc[mf][nf][1]);
            *reinterpret_cast<float2*>(O + (size_t)(rowi + 8) * 512 + colj) =
                make_float2(acc[mf][nf][2], acc[mf][nf][3]);
        }
    }

    if (!diag) {
        float* st = reinterpret_cast<float*>(sm);
#pragma unroll
        for (int sblk = 0; sblk < 4; sblk++) {
            __syncthreads();
            if (wm == sblk) {
#pragma unroll
                for (int mf = 0; mf < 2; mf++)
#pragma unroll
                    for (int nf = 0; nf < 8; nf++) {
                        int rl = mf * 16 + lr;
                        int col = wn * 64 + nf * 8 + 2 * lc;
                        st[rl * 132 + col]           = acc[mf][nf][0];
                        st[rl * 132 + col + 1]       = acc[mf][nf][1];
                        st[(rl + 8) * 132 + col]     = acc[mf][nf][2];
                        st[(rl + 8) * 132 + col + 1] = acc[mf][nf][3];
                    }
            }
            __syncthreads();
#pragma unroll 4
            for (int idx = tid; idx < 128 * 32; idx += 256) {
                int nn = idx >> 5, rl = idx & 31;
                O[(size_t)(j0 + nn) * 512 + i0 + sblk * 32 + rl] = st[rl * 132 + nn];
            }
        }
    }
}

// ============================================================
// K3: fused gather + channel-LN + final projection + gating.
//     256 thr, 64-j tiles, weights via __ldg (L1), 3 CTAs/SM.
// ============================================================
__global__ void __launch_bounds__(256, 3)
fusedC(const float* __restrict__ ong, const float* __restrict__ onb,
       const float* __restrict__ ob, float* __restrict__ out) {
    extern __shared__ uint32_t sm[];
    float* sO = reinterpret_cast<float*>(sm);      // [c 128][jj 64], pitch PO
    __shared__ float ps[4][64], pq[4][64], mS[64], rS[64];

    const int tid = threadIdx.x;
    const int wid = tid >> 5, lane = tid & 31;
    const int wm = wid >> 2, wn = wid & 3;
    const int lr = lane >> 2, lc = lane & 3;
    const int i = blockIdx.y, j0 = blockIdx.x * 64;

    // gather o tile [c][jj] (coalesced 256B rows per c)
#pragma unroll
    for (int e = 0; e < 8; e++) {
        int idx = tid + 256 * e;       // 2048 float4
        int c = idx >> 4, j4 = idx & 15;
        float4 v = reinterpret_cast<const float4*>(g_o + (size_t)c * LL + (size_t)i * 512 + j0)[j4];
        *reinterpret_cast<float4*>(sO + c * PO + j4 * 4) = v;
    }
    __syncthreads();

    // channel reduce: 4 partials per column
    {
        int col = tid & 63, qtr = tid >> 6;
        float s = 0.0f, q = 0.0f;
#pragma unroll 8
        for (int c = qtr * 32; c < qtr * 32 + 32; c++) {
            float v = sO[c * PO + col];
            s += v; q += v * v;
        }
        ps[qtr][col] = s; pq[qtr][col] = q;
    }
    __syncthreads();
    if (tid < 64) {
        float ss = ps[0][tid] + ps[1][tid] + ps[2][tid] + ps[3][tid];
        float qq = pq[0][tid] + pq[1][tid] + pq[2][tid] + pq[3][tid];
        float mean = ss * (1.0f / 128.0f);
        float var  = qq * (1.0f / 128.0f) - mean * mean;
        mS[tid] = mean;
        rS[tid] = rsqrtf(var + 1e-5f);
    }
    __syncthreads();

    // normalize in place -> tf32 bits
#pragma unroll 8
    for (int e = 0; e < 32; e++) {
        int idx = tid + 256 * e;       // 8192 elems
        int jj = idx & 63, c = idx >> 6;
        float v = (sO[c * PO + jj] - mS[jj]) * rS[jj] * __ldg(ong + c) + __ldg(onb + c);
        sm[c * PO + jj] = f2tf(v);
    }
    __syncthreads();

    // GEMM: rows = jj (A from sm[k=c][row=jj]), K = c, B via __ldg (L1)
    float acc[2][4][4];
#pragma unroll
    for (int mf = 0; mf < 2; mf++)
#pragma unroll
        for (int nf = 0; nf < 4; nf++)
#pragma unroll
            for (int v = 0; v < 4; v++) acc[mf][nf][v] = 0.0f;

#pragma unroll
    for (int ks = 0; ks < 16; ks++) {
        int kb = ks * 8;
        uint32_t a[2][4];
#pragma unroll
        for (int mf = 0; mf < 2; mf++) {
            int row = wm * 32 + mf * 16 + lr;
            a[mf][0] = sm[(kb + lc) * PO + row];
            a[mf][1] = sm[(kb + lc) * PO + row + 8];
            a[mf][2] = sm[(kb + 4 + lc) * PO + row];
            a[mf][3] = sm[(kb + 4 + lc) * PO + row + 8];
        }
#pragma unroll
        for (int nf = 0; nf < 4; nf++) {
            int col = wn * 32 + nf * 8 + lr;
            uint2 b = __ldg(reinterpret_cast<const uint2*>(g_owt + col * 128 + kb + 2 * lc));
            mma8(acc[0][nf], a[0], b.x, b.y);
            mma8(acc[1][nf], a[1], b.x, b.y);
        }
    }

    const size_t grow = (size_t)i * 512 + j0;
#pragma unroll
    for (int mf = 0; mf < 2; mf++) {
#pragma unroll
        for (int nf = 0; nf < 4; nf++) {
            size_t row = grow + wm * 32 + mf * 16 + lr;
            int col = wn * 32 + nf * 8 + 2 * lc;
            float b0v = __ldg(ob + col), b1v = __ldg(ob + col + 1);
            float2 gt0 = *reinterpret_cast<const float2*>(g_gate + row * 128 + col);
            float2 gt1 = *reinterpret_cast<const float2*>(g_gate + (row + 8) * 128 + col);
            *reinterpret_cast<float2*>(out + row * 128 + col) =
                make_float2((acc[mf][nf][0] + b0v) * gt0.x, (acc[mf][nf][1] + b1v) * gt0.y);
            *reinterpret_cast<float2*>(out + (row + 8) * 128 + col) =
                make_float2((acc[mf][nf][2] + b0v) * gt1.x, (acc[mf][nf][3] + b1v) * gt1.y);
        }
    }
}

// ============================================================
// launch
// ============================================================
extern "C" void kernel_launch(void* const* d_in, const int* in_sizes, int n_in,
                              void* d_out, int out_size) {
    const float* z      = (const float*)d_in[0];
    const float* norm_g = (const float*)d_in[1];
    const float* norm_b = (const float*)d_in[2];
    const float* a_w    = (const float*)d_in[3];
    const float* a_b    = (const float*)d_in[4];
    const float* ag_w   = (const float*)d_in[5];
    const float* ag_b   = (const float*)d_in[6];
    const float* onorm_g= (const float*)d_in[7];
    const float* onorm_b= (const float*)d_in[8];
    const float* o_w    = (const float*)d_in[9];
    const float* o_b    = (const float*)d_in[10];
    const float* g_wp   = (const float*)d_in[11];
    const float* g_bp   = (const float*)d_in[12];
    float* out = (float*)d_out;

    const int SMA = 64 * PZ * 4;           // 34.8 KB
    const int SMS = 2 * 2 * 128 * PS * 4;  // 81.9 KB
    const int SMC = 128 * PO * 4;          // 36.9 KB

    static bool attr_done = false;
    if (!attr_done) {
        cudaFuncSetAttribute(syrk_mma, cudaFuncAttributeMaxDynamicSharedMemorySize, SMS);
        attr_done = true;
    }

    prep_w<<<128, 512>>>(a_w, ag_w, g_wp, o_w);
    fusedA<<<LL / 64, 256, SMA>>>(z, norm_g, norm_b, a_b, ag_b, g_bp);
    syrk_mma<<<dim3(10, 128), 256, SMS>>>();
    fusedC<<<dim3(8, L), 256, SMC>>>(onorm_g, onorm_b, o_b, out);
}

// round 7
// speedup vs baseline: 1.2953x; 1.1361x over previous
#include <cuda_runtime.h>
#include <math.h>
#include <stdint.h>

#define L 512
#define LL (L*L)
#define PZ 136   // tf32 tile pitch (mod 32 == 8 words -> conflict-free uint2 frags)
#define PO 68    // fusedC gather tile pitch (mod 32 == 4)
#define PS 40    // syrk chunk pitch (mod 32 == 8)

// ---- scratch (device globals; allocation-free contract) ----
__device__ float    g_gate[(size_t)LL*128]; // frag-major float2 layout
__device__ uint32_t g_at  [(size_t)128*LL]; // gated a, tf32 bits, l-dim k-permuted
__device__ float    g_o   [(size_t)128*LL];
__device__ uint32_t g_awt [128*128];        // tf32 weights, fragment-major
__device__ uint32_t g_agwt[128*128];
__device__ uint32_t g_gwt [128*128];
__device__ uint32_t g_owt [128*128];

__device__ __forceinline__ float sigmoidf_(float x) { return 1.0f / (1.0f + expf(-x)); }

__device__ __forceinline__ uint32_t f2tf(float f) {
    uint32_t u;
    asm("cvt.rna.tf32.f32 %0, %1;" : "=r"(u) : "f"(f));
    return u;
}

// permute k within 8-group: order 0,4,1,5,2,6,3,7
__device__ __forceinline__ int kperm(int k) {
    return (k & ~7) | (((k & 3) << 1) | ((k >> 2) & 1));
}

// frag-major float2 index for gate[(row, col even pair)]
__device__ __forceinline__ size_t gate_fi(size_t row, int col) {
    return ((row >> 4) * 16 + (size_t)(col >> 3)) * 64 +
           ((row >> 3) & 1) * 32 + (row & 7) * 4 + ((col & 7) >> 1);
}

__device__ __forceinline__ void mma8(float* c, const uint32_t* a, uint32_t b0, uint32_t b1) {
    asm volatile(
        "mma.sync.aligned.m16n8k8.row.col.f32.tf32.tf32.f32 "
        "{%0,%1,%2,%3}, {%4,%5,%6,%7}, {%8,%9}, {%0,%1,%2,%3};\n"
        : "+f"(c[0]), "+f"(c[1]), "+f"(c[2]), "+f"(c[3])
        : "r"(a[0]), "r"(a[1]), "r"(a[2]), "r"(a[3]), "r"(b0), "r"(b1));
}

__device__ __forceinline__ void cpa16(void* dst, const void* src) {
    uint32_t s = (uint32_t)__cvta_generic_to_shared(dst);
    asm volatile("cp.async.cg.shared.global [%0], [%1], 16;\n" :: "r"(s), "l"(src));
}
__device__ __forceinline__ void cpa_commit() { asm volatile("cp.async.commit_group;\n" ::: "memory"); }
template<int N> __device__ __forceinline__ void cpa_wait() {
    asm volatile("cp.async.wait_group %0;\n" :: "n"(N) : "memory");
}

// ============================================================
// K0: pre-convert weights to tf32, FRAGMENT-MAJOR layout:
//     uint2 slot (g, ks, lane) holds W[g*8+lr][ks*8+lc] and [..][+4]
// ============================================================
__global__ void prep_w(const float* __restrict__ aw, const float* __restrict__ agw,
                       const float* __restrict__ gw, const float* __restrict__ ow) {
    int idx = blockIdx.x * 512 + threadIdx.x;   // 32768 total (4 x 8192 uint2)
    int w = idx >> 13, i = idx & 8191;
    int lane = i & 31, ks = (i >> 5) & 15, g = i >> 9;
    int lr = lane >> 2, lc = lane & 3;
    const float* src = (w == 0) ? aw : (w == 1) ? agw : (w == 2) ? gw : ow;
    uint32_t* dst = (w == 0) ? g_awt : (w == 1) ? g_agwt : (w == 2) ? g_gwt : g_owt;
    int srow = g * 8 + lr, k0 = ks * 8 + lc;
    dst[i * 2]     = f2tf(src[srow * 128 + k0]);
    dst[i * 2 + 1] = f2tf(src[srow * 128 + k0 + 4]);
}

// ============================================================
// K1: fused LN + dual GEMM (a,ag) + gating + direct permuted
//     transposed store of a + gate GEMM. 256 thr, 64-row tile.
//     Weights frag-major via __ldg; gate stored frag-major.
// ============================================================
__global__ void __launch_bounds__(256, 2)
fusedA(const float* __restrict__ z, const float* __restrict__ ng, const float* __restrict__ nb,
       const float* __restrict__ ab, const float* __restrict__ agb, const float* __restrict__ gb) {
    extern __shared__ uint32_t sZ[];   // 64 * PZ tf32 zn (k-permuted)
    const int tid = threadIdx.x;
    const int wid = tid >> 5, lane = tid & 31;
    const int lr = lane >> 2, lc = lane & 3;
    const size_t m0 = (size_t)blockIdx.x * 64;

    const uint2* WA = reinterpret_cast<const uint2*>(g_awt);
    const uint2* WQ = reinterpret_cast<const uint2*>(g_agwt);
    const uint2* WG = reinterpret_cast<const uint2*>(g_gwt);
    float2* GATE2 = reinterpret_cast<float2*>(g_gate);

    // LayerNorm: warp w handles rows [8w, 8w+8); write k-permuted
    {
        float4 g4 = reinterpret_cast<const float4*>(ng)[lane];
        float4 b4 = reinterpret_cast<const float4*>(nb)[lane];
        const int sgrp = (lane >> 1) * 8 + (lane & 1);
#pragma unroll
        for (int it = 0; it < 8; it++) {
            int row = wid * 8 + it;
            float4 v = reinterpret_cast<const float4*>(z)[(m0 + row) * 32 + lane];
            float s = v.x + v.y + v.z + v.w;
            float q = v.x*v.x + v.y*v.y + v.z*v.z + v.w*v.w;
#pragma unroll
            for (int o = 16; o > 0; o >>= 1) {
                s += __shfl_xor_sync(0xffffffffu, s, o);
                q += __shfl_xor_sync(0xffffffffu, q, o);
            }
            float mean = s * (1.0f / 128.0f);
            float var  = q * (1.0f / 128.0f) - mean * mean;
            float rs   = rsqrtf(var + 1e-5f);
            uint32_t* d = sZ + row * PZ + sgrp;
            d[0] = f2tf((v.x - mean) * rs * g4.x + b4.x);
            d[2] = f2tf((v.y - mean) * rs * g4.y + b4.y);
            d[4] = f2tf((v.z - mean) * rs * g4.z + b4.z);
            d[6] = f2tf((v.w - mean) * rs * g4.w + b4.w);
        }
    }
    __syncthreads();

    // ---- dual GEMM: acc_a = zn@a_w^T, acc_q = zn@ag_w^T ----
    float acc_a[4][2][4], acc_q[4][2][4];
#pragma unroll
    for (int mf = 0; mf < 4; mf++)
#pragma unroll
        for (int nf = 0; nf < 2; nf++)
#pragma unroll
            for (int v = 0; v < 4; v++) { acc_a[mf][nf][v] = 0.0f; acc_q[mf][nf][v] = 0.0f; }

#pragma unroll
    for (int ks = 0; ks < 16; ks++) {
        int kb = ks * 8;
        uint32_t a[4][4];
#pragma unroll
        for (int mf = 0; mf < 4; mf++) {
            int row = mf * 16 + lr;
            uint2 lo = *reinterpret_cast<const uint2*>(sZ + row * PZ + kb + 2 * lc);
            uint2 hi = *reinterpret_cast<const uint2*>(sZ + (row + 8) * PZ + kb + 2 * lc);
            a[mf][0] = lo.x; a[mf][1] = hi.x; a[mf][2] = lo.y; a[mf][3] = hi.y;
        }
#pragma unroll
        for (int nf = 0; nf < 2; nf++) {
            int g = wid * 2 + nf;
            uint2 ba = __ldg(WA + g * 512 + ks * 32 + lane);
            uint2 bq = __ldg(WQ + g * 512 + ks * 32 + lane);
#pragma unroll
            for (int mf = 0; mf < 4; mf++) {
                mma8(acc_a[mf][nf], a[mf], ba.x, ba.y);
                mma8(acc_q[mf][nf], a[mf], bq.x, bq.y);
            }
        }
    }

    // epilogue: P = (a + ab) * sigmoid(q + agb) -> tf32 -> g_at (sector-full scatter)
#pragma unroll
    for (int nf = 0; nf < 2; nf++) {
        int col = wid * 16 + nf * 8 + 2 * lc;
        float ba0 = __ldg(ab + col),  ba1 = __ldg(ab + col + 1);
        float bq0 = __ldg(agb + col), bq1 = __ldg(agb + col + 1);
        const size_t c0 = (size_t)col * LL + m0;
        const size_t c1 = (size_t)(col + 1) * LL + m0;
#pragma unroll
        for (int mf = 0; mf < 4; mf++) {
            int r0 = kperm(mf * 16 + lr), r1 = kperm(mf * 16 + 8 + lr);
            g_at[c0 + r0] = f2tf((acc_a[mf][nf][0] + ba0) * sigmoidf_(acc_q[mf][nf][0] + bq0));
            g_at[c1 + r0] = f2tf((acc_a[mf][nf][1] + ba1) * sigmoidf_(acc_q[mf][nf][1] + bq1));
            g_at[c0 + r1] = f2tf((acc_a[mf][nf][2] + ba0) * sigmoidf_(acc_q[mf][nf][2] + bq0));
            g_at[c1 + r1] = f2tf((acc_a[mf][nf][3] + ba1) * sigmoidf_(acc_q[mf][nf][3] + bq1));
        }
    }

    // ---- gate GEMM (sZ unmodified; no sync needed) ----
    float acc_g[4][2][4];
#pragma unroll
    for (int mf = 0; mf < 4; mf++)
#pragma unroll
        for (int nf = 0; nf < 2; nf++)
#pragma unroll
            for (int v = 0; v < 4; v++) acc_g[mf][nf][v] = 0.0f;

#pragma unroll
    for (int ks = 0; ks < 16; ks++) {
        int kb = ks * 8;
        uint32_t a[4][4];
#pragma unroll
        for (int mf = 0; mf < 4; mf++) {
            int row = mf * 16 + lr;
            uint2 lo = *reinterpret_cast<const uint2*>(sZ + row * PZ + kb + 2 * lc);
            uint2 hi = *reinterpret_cast<const uint2*>(sZ + (row + 8) * PZ + kb + 2 * lc);
            a[mf][0] = lo.x; a[mf][1] = hi.x; a[mf][2] = lo.y; a[mf][3] = hi.y;
        }
#pragma unroll
        for (int nf = 0; nf < 2; nf++) {
            int g = wid * 2 + nf;
            uint2 bg = __ldg(WG + g * 512 + ks * 32 + lane);
#pragma unroll
            for (int mf = 0; mf < 4; mf++)
                mma8(acc_g[mf][nf], a[mf], bg.x, bg.y);
        }
    }

    // gate stored frag-major (coalesced float2)
#pragma unroll
    for (int nf = 0; nf < 2; nf++) {
        int col = wid * 16 + nf * 8 + 2 * lc;
        float b0v = __ldg(gb + col), b1v = __ldg(gb + col + 1);
#pragma unroll
        for (int mf = 0; mf < 4; mf++) {
            size_t row = m0 + mf * 16 + lr;
            size_t fi = gate_fi(row, col);
            GATE2[fi]      = make_float2(sigmoidf_(acc_g[mf][nf][0] + b0v),
                                         sigmoidf_(acc_g[mf][nf][1] + b1v));
            GATE2[fi + 32] = make_float2(sigmoidf_(acc_g[mf][nf][2] + b0v),
                                         sigmoidf_(acc_g[mf][nf][3] + b1v));
        }
    }
}

// ============================================================
// K2: tf32 SYRK per channel, cp.async double-buffered. 256 thr.
//     Mirror written directly from registers (4 full sectors/STG).
// ============================================================
__global__ void __launch_bounds__(256, 2)
syrk_mma() {
    extern __shared__ uint32_t sm[];
    const int tid  = threadIdx.x;
    const int wid  = tid >> 5, lane = tid & 31;
    const int wm   = wid >> 1, wn = wid & 1;
    const int lr   = lane >> 2, lc = lane & 3;

    const int c = blockIdx.y;
    int rem = blockIdx.x, bi = 0, span = 4;
    while (rem >= span) { rem -= span; span--; bi++; }
    int bj = bi + rem;
    const int i0 = bi * 128, j0 = bj * 128;
    const bool diag = (bi == bj);

    const uint32_t* __restrict__ Ag = g_at + (size_t)c * LL;
    float* __restrict__ O = g_o + (size_t)c * LL;

    const int STG_SZ = 2 * 128 * PS;

    auto load_chunk = [&](int kc, int buf) {
        uint32_t* sA = sm + buf * STG_SZ;
        uint32_t* sB = sA + 128 * PS;
#pragma unroll
        for (int e = 0; e < 4; e++) {
            int idx = tid + 256 * e;
            int r = idx >> 3, c4 = idx & 7;
            cpa16(sA + r * PS + c4 * 4, Ag + (size_t)(i0 + r) * 512 + kc * 32 + c4 * 4);
            if (!diag)
                cpa16(sB + r * PS + c4 * 4, Ag + (size_t)(j0 + r) * 512 + kc * 32 + c4 * 4);
        }
        cpa_commit();
    };

    float acc[2][8][4];
#pragma unroll
    for (int mf = 0; mf < 2; mf++)
#pragma unroll
        for (int nf = 0; nf < 8; nf++)
#pragma unroll
            for (int v = 0; v < 4; v++) acc[mf][nf][v] = 0.0f;

    load_chunk(0, 0);

    for (int kc = 0; kc < 16; kc++) {
        if (kc + 1 < 16) { load_chunk(kc + 1, (kc + 1) & 1); cpa_wait<1>(); }
        else             { cpa_wait<0>(); }
        __syncthreads();
        const uint32_t* sA = sm + (kc & 1) * STG_SZ;
        const uint32_t* sB = diag ? sA : sA + 128 * PS;
#pragma unroll
        for (int ks = 0; ks < 4; ks++) {
            int kb = ks * 8;
            uint32_t a[2][4];
#pragma unroll
            for (int mf = 0; mf < 2; mf++) {
                int row = wm * 32 + mf * 16 + lr;
                uint2 lo = *reinterpret_cast<const uint2*>(sA + row * PS + kb + 2 * lc);
                uint2 hi = *reinterpret_cast<const uint2*>(sA + (row + 8) * PS + kb + 2 * lc);
                a[mf][0] = lo.x; a[mf][1] = hi.x; a[mf][2] = lo.y; a[mf][3] = hi.y;
            }
#pragma unroll
            for (int nf = 0; nf < 8; nf++) {
                int col = wn * 64 + nf * 8 + lr;
                uint2 b = *reinterpret_cast<const uint2*>(sB + col * PS + kb + 2 * lc);
                mma8(acc[0][nf], a[0], b.x, b.y);
                mma8(acc[1][nf], a[1], b.x, b.y);
            }
        }
        __syncthreads();
    }

    // direct tile write
#pragma unroll
    for (int mf = 0; mf < 2; mf++) {
#pragma unroll
        for (int nf = 0; nf < 8; nf++) {
            int rowi = i0 + wm * 32 + mf * 16 + lr;
            int colj = j0 + wn * 64 + nf * 8 + 2 * lc;
            *reinterpret_cast<float2*>(O + (size_t)rowi * 512 + colj) =
                make_float2(acc[mf][nf][0], acc[mf][nf][1]);
            *reinterpret_cast<float2*>(O + (size_t)(rowi + 8) * 512 + colj) =
                make_float2(acc[mf][nf][2], acc[mf][nf][3]);
        }
    }

    // mirror: direct register stores (4 full 32B sectors per STG)
    if (!diag) {
#pragma unroll
        for (int mf = 0; mf < 2; mf++) {
#pragma unroll
            for (int nf = 0; nf < 8; nf++) {
                int r  = wm * 32 + mf * 16 + lr;
                int cA = wn * 64 + nf * 8 + 2 * lc;
                O[(size_t)(j0 + cA) * 512 + i0 + r]         = acc[mf][nf][0];
                O[(size_t)(j0 + cA + 1) * 512 + i0 + r]     = acc[mf][nf][1];
                O[(size_t)(j0 + cA) * 512 + i0 + r + 8]     = acc[mf][nf][2];
                O[(size_t)(j0 + cA + 1) * 512 + i0 + r + 8] = acc[mf][nf][3];
            }
        }
    }
}

// ============================================================
// K3: fused gather + channel-LN + final projection + gating.
//     256 thr; A transposed+permuted in smem; frag-major gate &
//     weights; output staged through smem for coalesced stores.
// ============================================================
__global__ void __launch_bounds__(256, 3)
fusedC(const float* __restrict__ ong, const float* __restrict__ onb,
       const float* __restrict__ ob, float* __restrict__ out) {
    extern __shared__ uint32_t sm[];
    float*    sO = reinterpret_cast<float*>(sm);   // [c 128][jj 64], pitch PO
    uint32_t* sT = sm + 128 * PO;                  // [jj 64][k-perm c], pitch PZ
    __shared__ float ps[4][64], pq[4][64], mS[64], rS[64];

    const int tid = threadIdx.x;
    const int wid = tid >> 5, lane = tid & 31;
    const int wm = wid >> 2, wn = wid & 3;
    const int lr = lane >> 2, lc = lane & 3;
    const int i = blockIdx.y, j0 = blockIdx.x * 64;

    const uint2* WO = reinterpret_cast<const uint2*>(g_owt);
    const float2* GATE2 = reinterpret_cast<const float2*>(g_gate);

    // gather o tile [c][jj]
#pragma unroll
    for (int e = 0; e < 8; e++) {
        int idx = tid + 256 * e;       // 2048 float4
        int c = idx >> 4, j4 = idx & 15;
        float4 v = reinterpret_cast<const float4*>(g_o + (size_t)c * LL + (size_t)i * 512 + j0)[j4];
        *reinterpret_cast<float4*>(sO + c * PO + j4 * 4) = v;
    }
    __syncthreads();

    // channel reduce
    {
        int col = tid & 63, qtr = tid >> 6;
        float s = 0.0f, q = 0.0f;
#pragma unroll 8
        for (int c = qtr * 32; c < qtr * 32 + 32; c++) {
            float v = sO[c * PO + col];
            s += v; q += v * v;
        }
        ps[qtr][col] = s; pq[qtr][col] = q;
    }
    __syncthreads();
    if (tid < 64) {
        float ss = ps[0][tid] + ps[1][tid] + ps[2][tid] + ps[3][tid];
        float qq = pq[0][tid] + pq[1][tid] + pq[2][tid] + pq[3][tid];
        float mean = ss * (1.0f / 128.0f);
        float var  = qq * (1.0f / 128.0f) - mean * mean;
        mS[tid] = mean;
        rS[tid] = rsqrtf(var + 1e-5f);
    }
    __syncthreads();

    // normalize -> transposed + k-permuted tf32 in sT
    {
        const int warp = wid;
#pragma unroll 8
        for (int e = 0; e < 32; e++) {
            int gidx = e * 8 + warp;                 // 256 groups of 8c x 4jj
            int c = (gidx & 15) * 8 + (lane & 7);
            int jj = (gidx >> 4) * 4 + (lane >> 3);
            float v = (sO[c * PO + jj] - mS[jj]) * rS[jj] * __ldg(ong + c) + __ldg(onb + c);
            sT[jj * PZ + kperm(c)] = f2tf(v);
        }
    }
    __syncthreads();

    // GEMM: rows = jj (vectorized frags from sT), K = c, B frag-major L1
    float acc[2][4][4];
#pragma unroll
    for (int mf = 0; mf < 2; mf++)
#pragma unroll
        for (int nf = 0; nf < 4; nf++)
#pragma unroll
            for (int v = 0; v < 4; v++) acc[mf][nf][v] = 0.0f;

#pragma unroll
    for (int ks = 0; ks < 16; ks++) {
        int kb = ks * 8;
        uint32_t a[2][4];
#pragma unroll
        for (int mf = 0; mf < 2; mf++) {
            int row = wm * 32 + mf * 16 + lr;
            uint2 lo = *reinterpret_cast<const uint2*>(sT + row * PZ + kb + 2 * lc);
            uint2 hi = *reinterpret_cast<const uint2*>(sT + (row + 8) * PZ + kb + 2 * lc);
            a[mf][0] = lo.x; a[mf][1] = hi.x; a[mf][2] = lo.y; a[mf][3] = hi.y;
        }
#pragma unroll
        for (int nf = 0; nf < 4; nf++) {
            int g = wn * 4 + nf;
            uint2 b = __ldg(WO + g * 512 + ks * 32 + lane);
            mma8(acc[0][nf], a[0], b.x, b.y);
            mma8(acc[1][nf], a[1], b.x, b.y);
        }
    }
    __syncthreads();   // all GEMM reads of sT done; reuse as output stage

    // epilogue: bias + gate (frag-major, coalesced), stage into sT
    const size_t grow = (size_t)i * 512 + j0;
    float* sR = reinterpret_cast<float*>(sT);
#pragma unroll
    for (int mf = 0; mf < 2; mf++) {
#pragma unroll
        for (int nf = 0; nf < 4; nf++) {
            int jj = wm * 32 + mf * 16 + lr;
            int col = wn * 32 + nf * 8 + 2 * lc;
            float b0v = __ldg(ob + col), b1v = __ldg(ob + col + 1);
            size_t fi = gate_fi(grow + jj, col);
            float2 gt0 = GATE2[fi], gt1 = GATE2[fi + 32];
            *reinterpret_cast<float2*>(sR + jj * PZ + col) =
                make_float2((acc[mf][nf][0] + b0v) * gt0.x, (acc[mf][nf][1] + b1v) * gt0.y);
            *reinterpret_cast<float2*>(sR + (jj + 8) * PZ + col) =
                make_float2((acc[mf][nf][2] + b0v) * gt1.x, (acc[mf][nf][3] + b1v) * gt1.y);
        }
    }
    __syncthreads();

    // coalesced output store
#pragma unroll 4
    for (int e = 0; e < 16; e++) {
        int idx = tid + 256 * e;       // 4096 float2
        int jj = idx >> 6, c2 = idx & 63;
        float2 v = *reinterpret_cast<const float2*>(sR + jj * PZ + 2 * c2);
        *reinterpret_cast<float2*>(out + (grow + jj) * 128 + 2 * c2) = v;
    }
}

// ============================================================
// launch
// ============================================================
extern "C" void kernel_launch(void* const* d_in, const int* in_sizes, int n_in,
                              void* d_out, int out_size) {
    const float* z      = (const float*)d_in[0];
    const float* norm_g = (const float*)d_in[1];
    const float* norm_b = (const float*)d_in[2];
    const float* a_w    = (const float*)d_in[3];
    const float* a_b    = (const float*)d_in[4];
    const float* ag_w   = (const float*)d_in[5];
    const float* ag_b   = (const float*)d_in[6];
    const float* onorm_g= (const float*)d_in[7];
    const float* onorm_b= (const float*)d_in[8];
    const float* o_w    = (const float*)d_in[9];
    const float* o_b    = (const float*)d_in[10];
    const float* g_wp   = (const float*)d_in[11];
    const float* g_bp   = (const float*)d_in[12];
    float* out = (float*)d_out;

    const int SMA = 64 * PZ * 4;                 // 34.8 KB
    const int SMS = 2 * 2 * 128 * PS * 4;        // 81.9 KB
    const int SMC = (128 * PO + 64 * PZ) * 4;    // 69.6 KB

    static bool attr_done = false;
    if (!attr_done) {
        cudaFuncSetAttribute(syrk_mma, cudaFuncAttributeMaxDynamicSharedMemorySize, SMS);
        cudaFuncSetAttribute(fusedC,   cudaFuncAttributeMaxDynamicSharedMemorySize, SMC);
        attr_done = true;
    }

    prep_w<<<64, 512>>>(a_w, ag_w, g_wp, o_w);
    fusedA<<<LL / 64, 256, SMA>>>(z, norm_g, norm_b, a_b, ag_b, g_bp);
    syrk_mma<<<dim3(10, 128), 256, SMS>>>();
    fusedC<<<dim3(8, L), 256, SMC>>>(onorm_g, onorm_b, o_b, out);
}

// round 10
// speedup vs baseline: 1.4634x; 1.1298x over previous
#include <cuda_runtime.h>
#include <cuda_fp16.h>
#include <math.h>
#include <stdint.h>

#define L 512
#define LL (L*L)
#define PZ 136   // tf32 tile pitch in words (mod 32 == 8 -> conflict-free uint2 frags)
#define PO 68    // fusedC gather tile pitch (floats)
#define PH 72    // fusedA fp16 staging pitch in HALVES (144B, 16B-aligned)
#define PS 40    // syrk chunk pitch in WORDS (80 halves per row slot, 64 used)

// ---- scratch (device globals; allocation-free contract) ----
__device__ float    g_gate[(size_t)LL*128]; // frag-major float2 layout
__device__ __half   g_at  [(size_t)128*LL]; // gated a, fp16, l-dim pair-permuted
__device__ float    g_o   [(size_t)128*LL];
__device__ uint32_t g_awt [128*128];        // tf32 weights, fragment-major
__device__ uint32_t g_agwt[128*128];
__device__ uint32_t g_gwt [128*128];
__device__ uint32_t g_owt [128*128];

__device__ __forceinline__ float sigmoidf_(float x) { return 1.0f / (1.0f + expf(-x)); }

__device__ __forceinline__ uint32_t f2tf(float f) {
    uint32_t u;
    asm("cvt.rna.tf32.f32 %0, %1;" : "=r"(u) : "f"(f));
    return u;
}

// tf32 k8 permutation (order 0,4,1,5,2,6,3,7) — used in fusedC smem only
__device__ __forceinline__ int kperm(int k) {
    return (k & ~7) | (((k & 3) << 1) | ((k >> 2) & 1));
}

// fp16 k16 pair permutation: [k0,k1,k8,k9,k2,k3,k10,k11,k4,k5,k12,k13,k6,k7,k14,k15]
__device__ __forceinline__ int p16(int k) {
    return (k & ~15) | (((k >> 1) & 3) << 2) | (((k >> 3) & 1) << 1) | (k & 1);
}

// frag-major float2 index for gate[(row, col even pair)]
__device__ __forceinline__ size_t gate_fi(size_t row, int col) {
    return ((row >> 4) * 16 + (size_t)(col >> 3)) * 64 +
           ((row >> 3) & 1) * 32 + (row & 7) * 4 + ((col & 7) >> 1);
}

__device__ __forceinline__ void mma8(float* c, const uint32_t* a, uint32_t b0, uint32_t b1) {
    asm volatile(
        "mma.sync.aligned.m16n8k8.row.col.f32.tf32.tf32.f32 "
        "{%0,%1,%2,%3}, {%4,%5,%6,%7}, {%8,%9}, {%0,%1,%2,%3};\n"
        : "+f"(c[0]), "+f"(c[1]), "+f"(c[2]), "+f"(c[3])
        : "r"(a[0]), "r"(a[1]), "r"(a[2]), "r"(a[3]), "r"(b0), "r"(b1));
}

// fp16 m16n8k16
__device__ __forceinline__ void mma16h(float* c, uint32_t a0, uint32_t a1,
                                       uint32_t a2, uint32_t a3,
                                       uint32_t b0, uint32_t b1) {
    asm volatile(
        "mma.sync.aligned.m16n8k16.row.col.f32.f16.f16.f32 "
        "{%0,%1,%2,%3}, {%4,%5,%6,%7}, {%8,%9}, {%0,%1,%2,%3};\n"
        : "+f"(c[0]), "+f"(c[1]), "+f"(c[2]), "+f"(c[3])
        : "r"(a0), "r"(a1), "r"(a2), "r"(a3), "r"(b0), "r"(b1));
}

__device__ __forceinline__ void cpa16(void* dst, const void* src) {
    uint32_t s = (uint32_t)__cvta_generic_to_shared(dst);
    asm volatile("cp.async.cg.shared.global [%0], [%1], 16;\n" :: "r"(s), "l"(src));
}
__device__ __forceinline__ void cpa_commit() { asm volatile("cp.async.commit_group;\n" ::: "memory"); }
template<int N> __device__ __forceinline__ void cpa_wait() {
    asm volatile("cp.async.wait_group %0;\n" :: "n"(N) : "memory");
}

// ============================================================
// K0: pre-convert weights to tf32, FRAGMENT-MAJOR layout
// ============================================================
__global__ void prep_w(const float* __restrict__ aw, const float* __restrict__ agw,
                       const float* __restrict__ gw, const float* __restrict__ ow) {
    int idx = blockIdx.x * 512 + threadIdx.x;   // 32768 total (4 x 8192 uint2)
    int w = idx >> 13, i = idx & 8191;
    int lane = i & 31, ks = (i >> 5) & 15, g = i >> 9;
    int lr = lane >> 2, lc = lane & 3;
    const float* src = (w == 0) ? aw : (w == 1) ? agw : (w == 2) ? gw : ow;
    uint32_t* dst = (w == 0) ? g_awt : (w == 1) ? g_agwt : (w == 2) ? g_gwt : g_owt;
    int srow = g * 8 + lr, k0 = ks * 8 + lc;
    dst[i * 2]     = f2tf(src[srow * 128 + k0]);
    dst[i * 2 + 1] = f2tf(src[srow * 128 + k0 + 4]);
}

// ============================================================
// K1: fused LN + dual GEMM (a,ag) + gating -> fp16 g_at (staged
//     via smem, pair-permuted, coalesced) + gate GEMM. 256 thr.
// ============================================================
__global__ void __launch_bounds__(256, 2)
fusedA(const float* __restrict__ z, const float* __restrict__ ng, const float* __restrict__ nb,
       const float* __restrict__ ab, const float* __restrict__ agb, const float* __restrict__ gb) {
    extern __shared__ uint32_t sm[];
    uint32_t* sZ = sm;                              // 64 * PZ tf32 zn (k-permuted)
    __half*   sP = reinterpret_cast<__half*>(sm + 64 * PZ);  // [col 128][row PH]
    const int tid = threadIdx.x;
    const int wid = tid >> 5, lane = tid & 31;
    const int lr = lane >> 2, lc = lane & 3;
    const size_t m0 = (size_t)blockIdx.x * 64;

    const uint2* WA = reinterpret_cast<const uint2*>(g_awt);
    const uint2* WQ = reinterpret_cast<const uint2*>(g_agwt);
    const uint2* WG = reinterpret_cast<const uint2*>(g_gwt);
    float2* GATE2 = reinterpret_cast<float2*>(g_gate);

    // LayerNorm: warp w handles rows [8w, 8w+8); write k-permuted (tf32 k8 perm)
    {
        float4 g4 = reinterpret_cast<const float4*>(ng)[lane];
        float4 b4 = reinterpret_cast<const float4*>(nb)[lane];
        const int sgrp = (lane >> 1) * 8 + (lane & 1);
#pragma unroll
        for (int it = 0; it < 8; it++) {
            int row = wid * 8 + it;
            float4 v = reinterpret_cast<const float4*>(z)[(m0 + row) * 32 + lane];
            float s = v.x + v.y + v.z + v.w;
            float q = v.x*v.x + v.y*v.y + v.z*v.z + v.w*v.w;
#pragma unroll
            for (int o = 16; o > 0; o >>= 1) {
                s += __shfl_xor_sync(0xffffffffu, s, o);
                q += __shfl_xor_sync(0xffffffffu, q, o);
            }
            float mean = s * (1.0f / 128.0f);
            float var  = q * (1.0f / 128.0f) - mean * mean;
            float rs   = rsqrtf(var + 1e-5f);
            uint32_t* d = sZ + row * PZ + sgrp;
            d[0] = f2tf((v.x - mean) * rs * g4.x + b4.x);
            d[2] = f2tf((v.y - mean) * rs * g4.y + b4.y);
            d[4] = f2tf((v.z - mean) * rs * g4.z + b4.z);
            d[6] = f2tf((v.w - mean) * rs * g4.w + b4.w);
        }
    }
    __syncthreads();

    // ---- dual GEMM: acc_a = zn@a_w^T, acc_q = zn@ag_w^T ----
    float acc_a[4][2][4], acc_q[4][2][4];
#pragma unroll
    for (int mf = 0; mf < 4; mf++)
#pragma unroll
        for (int nf = 0; nf < 2; nf++)
#pragma unroll
            for (int v = 0; v < 4; v++) { acc_a[mf][nf][v] = 0.0f; acc_q[mf][nf][v] = 0.0f; }

#pragma unroll
    for (int ks = 0; ks < 16; ks++) {
        int kb = ks * 8;
        uint32_t a[4][4];
#pragma unroll
        for (int mf = 0; mf < 4; mf++) {
            int row = mf * 16 + lr;
            uint2 lo = *reinterpret_cast<const uint2*>(sZ + row * PZ + kb + 2 * lc);
            uint2 hi = *reinterpret_cast<const uint2*>(sZ + (row + 8) * PZ + kb + 2 * lc);
            a[mf][0] = lo.x; a[mf][1] = hi.x; a[mf][2] = lo.y; a[mf][3] = hi.y;
        }
#pragma unroll
        for (int nf = 0; nf < 2; nf++) {
            int g = wid * 2 + nf;
            uint2 ba = __ldg(WA + g * 512 + ks * 32 + lane);
            uint2 bq = __ldg(WQ + g * 512 + ks * 32 + lane);
#pragma unroll
            for (int mf = 0; mf < 4; mf++) {
                mma8(acc_a[mf][nf], a[mf], ba.x, ba.y);
                mma8(acc_q[mf][nf], a[mf], bq.x, bq.y);
            }
        }
    }

    // epilogue: P = (a + ab) * sigmoid(q + agb) -> fp16 staged in sP (pair-perm rows)
#pragma unroll
    for (int nf = 0; nf < 2; nf++) {
        int col = wid * 16 + nf * 8 + 2 * lc;
        float ba0 = __ldg(ab + col),  ba1 = __ldg(ab + col + 1);
        float bq0 = __ldg(agb + col), bq1 = __ldg(agb + col + 1);
#pragma unroll
        for (int mf = 0; mf < 4; mf++) {
            int r0 = p16(mf * 16 + lr), r1 = p16(mf * 16 + 8 + lr);
            sP[col * PH + r0]       = __float2half_rn((acc_a[mf][nf][0] + ba0) * sigmoidf_(acc_q[mf][nf][0] + bq0));
            sP[(col + 1) * PH + r0] = __float2half_rn((acc_a[mf][nf][1] + ba1) * sigmoidf_(acc_q[mf][nf][1] + bq1));
            sP[col * PH + r1]       = __float2half_rn((acc_a[mf][nf][2] + ba0) * sigmoidf_(acc_q[mf][nf][2] + bq0));
            sP[(col + 1) * PH + r1] = __float2half_rn((acc_a[mf][nf][3] + ba1) * sigmoidf_(acc_q[mf][nf][3] + bq1));
        }
    }
    __syncthreads();

    // coalesced uint4 store of fp16 a-tile: 128 cols x 64 halves
#pragma unroll
    for (int e = 0; e < 4; e++) {
        int idx = tid + 256 * e;           // 1024 uint4
        int c = idx >> 3, e8 = idx & 7;    // 8 uint4 per col
        uint4 v = *reinterpret_cast<const uint4*>(sP + c * PH + e8 * 8);
        *reinterpret_cast<uint4*>(g_at + (size_t)c * LL + m0 + e8 * 8) = v;
    }

    // ---- gate GEMM (sZ unmodified) ----
    float acc_g[4][2][4];
#pragma unroll
    for (int mf = 0; mf < 4; mf++)
#pragma unroll
        for (int nf = 0; nf < 2; nf++)
#pragma unroll
            for (int v = 0; v < 4; v++) acc_g[mf][nf][v] = 0.0f;

#pragma unroll
    for (int ks = 0; ks < 16; ks++) {
        int kb = ks * 8;
        uint32_t a[4][4];
#pragma unroll
        for (int mf = 0; mf < 4; mf++) {
            int row = mf * 16 + lr;
            uint2 lo = *reinterpret_cast<const uint2*>(sZ + row * PZ + kb + 2 * lc);
            uint2 hi = *reinterpret_cast<const uint2*>(sZ + (row + 8) * PZ + kb + 2 * lc);
            a[mf][0] = lo.x; a[mf][1] = hi.x; a[mf][2] = lo.y; a[mf][3] = hi.y;
        }
#pragma unroll
        for (int nf = 0; nf < 2; nf++) {
            int g = wid * 2 + nf;
            uint2 bg = __ldg(WG + g * 512 + ks * 32 + lane);
#pragma unroll
            for (int mf = 0; mf < 4; mf++)
                mma8(acc_g[mf][nf], a[mf], bg.x, bg.y);
        }
    }

    // gate stored frag-major (coalesced float2)
#pragma unroll
    for (int nf = 0; nf < 2; nf++) {
        int col = wid * 16 + nf * 8 + 2 * lc;
        float b0v = __ldg(gb + col), b1v = __ldg(gb + col + 1);
#pragma unroll
        for (int mf = 0; mf < 4; mf++) {
            size_t row = m0 + mf * 16 + lr;
            size_t fi = gate_fi(row, col);
            GATE2[fi]      = make_float2(sigmoidf_(acc_g[mf][nf][0] + b0v),
                                         sigmoidf_(acc_g[mf][nf][1] + b1v));
            GATE2[fi + 32] = make_float2(sigmoidf_(acc_g[mf][nf][2] + b0v),
                                         sigmoidf_(acc_g[mf][nf][3] + b1v));
        }
    }
}

// ============================================================
// K2: fp16 SYRK per channel (m16n8k16, fp32 accum), cp.async
//     double-buffered, k-chunk 64. 256 thr.
// ============================================================
__global__ void __launch_bounds__(256, 2)
syrk_mma() {
    extern __shared__ uint32_t sm[];   // 2 stages x (A + B), pitch PS words/row
    const int tid  = threadIdx.x;
    const int wid  = tid >> 5, lane = tid & 31;
    const int wm   = wid >> 1, wn = wid & 1;
    const int lr   = lane >> 2, lc = lane & 3;

    const int c = blockIdx.y;
    int rem = blockIdx.x, bi = 0, span = 4;
    while (rem >= span) { rem -= span; span--; bi++; }
    int bj = bi + rem;
    const int i0 = bi * 128, j0 = bj * 128;
    const bool diag = (bi == bj);

    const __half* __restrict__ Ag = g_at + (size_t)c * LL;
    float* __restrict__ O = g_o + (size_t)c * LL;

    const int STG_SZ = 2 * 128 * PS;   // words per stage (A+B)

    auto load_chunk = [&](int kc, int buf) {
        uint32_t* sA = sm + buf * STG_SZ;
        uint32_t* sB = sA + 128 * PS;
#pragma unroll
        for (int e = 0; e < 4; e++) {
            int idx = tid + 256 * e;   // 1024 cpa16 per tile (128 rows x 128B)
            int r = idx >> 3, c8 = idx & 7;
            cpa16(sA + r * PS + c8 * 4, Ag + (size_t)(i0 + r) * 512 + kc * 64 + c8 * 8);
            if (!diag)
                cpa16(sB + r * PS + c8 * 4, Ag + (size_t)(j0 + r) * 512 + kc * 64 + c8 * 8);
        }
        cpa_commit();
    };

    float acc[2][8][4];
#pragma unroll
    for (int mf = 0; mf < 2; mf++)
#pragma unroll
        for (int nf = 0; nf < 8; nf++)
#pragma unroll
            for (int v = 0; v < 4; v++) acc[mf][nf][v] = 0.0f;

    load_chunk(0, 0);

    for (int kc = 0; kc < 8; kc++) {
        if (kc + 1 < 8) { load_chunk(kc + 1, (kc + 1) & 1); cpa_wait<1>(); }
        else            { cpa_wait<0>(); }
        __syncthreads();
        const uint32_t* sA = sm + (kc & 1) * STG_SZ;
        const uint32_t* sB = diag ? sA : sA + 128 * PS;
#pragma unroll
        for (int g = 0; g < 4; g++) {       // 4 k16-groups per chunk
            int kb = g * 8;                 // word offset
            uint32_t a[2][4];
#pragma unroll
            for (int mf = 0; mf < 2; mf++) {
                int row = wm * 32 + mf * 16 + lr;
                uint2 lo = *reinterpret_cast<const uint2*>(sA + row * PS + kb + 2 * lc);
                uint2 hi = *reinterpret_cast<const uint2*>(sA + (row + 8) * PS + kb + 2 * lc);
                a[mf][0] = lo.x; a[mf][1] = hi.x; a[mf][2] = lo.y; a[mf][3] = hi.y;
            }
#pragma unroll
            for (int nf = 0; nf < 8; nf++) {
                int col = wn * 64 + nf * 8 + lr;
                uint2 b = *reinterpret_cast<const uint2*>(sB + col * PS + kb + 2 * lc);
                mma16h(acc[0][nf], a[0][0], a[0][1], a[0][2], a[0][3], b.x, b.y);
                mma16h(acc[1][nf], a[1][0], a[1][1], a[1][2], a[1][3], b.x, b.y);
            }
        }
        __syncthreads();
    }

    // direct tile write
#pragma unroll
    for (int mf = 0; mf < 2; mf++) {
#pragma unroll
        for (int nf = 0; nf < 8; nf++) {
            int rowi = i0 + wm * 32 + mf * 16 + lr;
            int colj = j0 + wn * 64 + nf * 8 + 2 * lc;
            *reinterpret_cast<float2*>(O + (size_t)rowi * 512 + colj) =
                make_float2(acc[mf][nf][0], acc[mf][nf][1]);
            *reinterpret_cast<float2*>(O + (size_t)(rowi + 8) * 512 + colj) =
                make_float2(acc[mf][nf][2], acc[mf][nf][3]);
        }
    }

    // mirror: direct register stores (4 full 32B sectors per STG)
    if (!diag) {
#pragma unroll
        for (int mf = 0; mf < 2; mf++) {
#pragma unroll
            for (int nf = 0; nf < 8; nf++) {
                int r  = wm * 32 + mf * 16 + lr;
                int cA = wn * 64 + nf * 8 + 2 * lc;
                O[(size_t)(j0 + cA) * 512 + i0 + r]         = acc[mf][nf][0];
                O[(size_t)(j0 + cA + 1) * 512 + i0 + r]     = acc[mf][nf][1];
                O[(size_t)(j0 + cA) * 512 + i0 + r + 8]     = acc[mf][nf][2];
                O[(size_t)(j0 + cA + 1) * 512 + i0 + r + 8] = acc[mf][nf][3];
            }
        }
    }
}

// ============================================================
// K3: fused gather + channel-LN + final projection + gating.
// ============================================================
__global__ void __launch_bounds__(256, 3)
fusedC(const float* __restrict__ ong, const float* __restrict__ onb,
       const float* __restrict__ ob, float* __restrict__ out) {
    extern __shared__ uint32_t sm[];
    float*    sO = reinterpret_cast<float*>(sm);   // [c 128][jj 64], pitch PO
    uint32_t* sT = sm + 128 * PO;                  // [jj 64][k-perm c], pitch PZ
    __shared__ float ps[4][64], pq[4][64], mS[64], rS[64];

    const int tid = threadIdx.x;
    const int wid = tid >> 5, lane = tid & 31;
    const int wm = wid >> 2, wn = wid & 3;
    const int lr = lane >> 2, lc = lane & 3;
    const int i = blockIdx.y, j0 = blockIdx.x * 64;

    const uint2* WO = reinterpret_cast<const uint2*>(g_owt);
    const float2* GATE2 = reinterpret_cast<const float2*>(g_gate);

    // gather o tile [c][jj]
#pragma unroll
    for (int e = 0; e < 8; e++) {
        int idx = tid + 256 * e;       // 2048 float4
        int c = idx >> 4, j4 = idx & 15;
        float4 v = reinterpret_cast<const float4*>(g_o + (size_t)c * LL + (size_t)i * 512 + j0)[j4];
        *reinterpret_cast<float4*>(sO + c * PO + j4 * 4) = v;
    }
    __syncthreads();

    // channel reduce
    {
        int col = tid & 63, qtr = tid >> 6;
        float s = 0.0f, q = 0.0f;
#pragma unroll 8
        for (int c = qtr * 32; c < qtr * 32 + 32; c++) {
            float v = sO[c * PO + col];
            s += v; q += v * v;
        }
        ps[qtr][col] = s; pq[qtr][col] = q;
    }
    __syncthreads();
    if (tid < 64) {
        float ss = ps[0][tid] + ps[1][tid] + ps[2][tid] + ps[3][tid];
        float qq = pq[0][tid] + pq[1][tid] + pq[2][tid] + pq[3][tid];
        float mean = ss * (1.0f / 128.0f);
        float var  = qq * (1.0f / 128.0f) - mean * mean;
        mS[tid] = mean;
        rS[tid] = rsqrtf(var + 1e-5f);
    }
    __syncthreads();

    // normalize -> transposed + k-permuted tf32 in sT
    {
        const int warp = wid;
#pragma unroll 8
        for (int e = 0; e < 32; e++) {
            int gidx = e * 8 + warp;
            int c = (gidx & 15) * 8 + (lane & 7);
            int jj = (gidx >> 4) * 4 + (lane >> 3);
            float v = (sO[c * PO + jj] - mS[jj]) * rS[jj] * __ldg(ong + c) + __ldg(onb + c);
            sT[jj * PZ + kperm(c)] = f2tf(v);
        }
    }
    __syncthreads();

    // GEMM: rows = jj, K = c, B frag-major L1
    float acc[2][4][4];
#pragma unroll
    for (int mf = 0; mf < 2; mf++)
#pragma unroll
        for (int nf = 0; nf < 4; nf++)
#pragma unroll
            for (int v = 0; v < 4; v++) acc[mf][nf][v] = 0.0f;

#pragma unroll
    for (int ks = 0; ks < 16; ks++) {
        int kb = ks * 8;
        uint32_t a[2][4];
#pragma unroll
        for (int mf = 0; mf < 2; mf++) {
            int row = wm * 32 + mf * 16 + lr;
            uint2 lo = *reinterpret_cast<const uint2*>(sT + row * PZ + kb + 2 * lc);
            uint2 hi = *reinterpret_cast<const uint2*>(sT + (row + 8) * PZ + kb + 2 * lc);
            a[mf][0] = lo.x; a[mf][1] = hi.x; a[mf][2] = lo.y; a[mf][3] = hi.y;
        }
#pragma unroll
        for (int nf = 0; nf < 4; nf++) {
            int g = wn * 4 + nf;
            uint2 b = __ldg(WO + g * 512 + ks * 32 + lane);
            mma8(acc[0][nf], a[0], b.x, b.y);
            mma8(acc[1][nf], a[1], b.x, b.y);
        }
    }
    __syncthreads();   // reuse sT as output stage

    // epilogue: bias + gate (frag-major), stage into sT
    const size_t grow = (size_t)i * 512 + j0;
    float* sR = reinterpret_cast<float*>(sT);
#pragma unroll
    for (int mf = 0; mf < 2; mf++) {
#pragma unroll
        for (int nf = 0; nf < 4; nf++) {
            int jj = wm * 32 + mf * 16 + lr;
            int col = wn * 32 + nf * 8 + 2 * lc;
            float b0v = __ldg(ob + col), b1v = __ldg(ob + col + 1);
            size_t fi = gate_fi(grow + jj, col);
            float2 gt0 = GATE2[fi], gt1 = GATE2[fi + 32];
            *reinterpret_cast<float2*>(sR + jj * PZ + col) =
                make_float2((acc[mf][nf][0] + b0v) * gt0.x, (acc[mf][nf][1] + b1v) * gt0.y);
            *reinterpret_cast<float2*>(sR + (jj + 8) * PZ + col) =
                make_float2((acc[mf][nf][2] + b0v) * gt1.x, (acc[mf][nf][3] + b1v) * gt1.y);
        }
    }
    __syncthreads();

    // coalesced output store
#pragma unroll 4
    for (int e = 0; e < 16; e++) {
        int idx = tid + 256 * e;
        int jj = idx >> 6, c2 = idx & 63;
        float2 v = *reinterpret_cast<const float2*>(sR + jj * PZ + 2 * c2);
        *reinterpret_cast<float2*>(out + (grow + jj) * 128 + 2 * c2) = v;
    }
}

// ============================================================
// launch
// ============================================================
extern "C" void kernel_launch(void* const* d_in, const int* in_sizes, int n_in,
                              void* d_out, int out_size) {
    const float* z      = (const float*)d_in[0];
    const float* norm_g = (const float*)d_in[1];
    const float* norm_b = (const float*)d_in[2];
    const float* a_w    = (const float*)d_in[3];
    const float* a_b    = (const float*)d_in[4];
    const float* ag_w   = (const float*)d_in[5];
    const float* ag_b   = (const float*)d_in[6];
    const float* onorm_g= (const float*)d_in[7];
    const float* onorm_b= (const float*)d_in[8];
    const float* o_w    = (const float*)d_in[9];
    const float* o_b    = (const float*)d_in[10];
    const float* g_wp   = (const float*)d_in[11];
    const float* g_bp   = (const float*)d_in[12];
    float* out = (float*)d_out;

    const int SMA = 64 * PZ * 4 + 128 * PH * 2;  // 52.9 KB (>48K: attr set below)
    const int SMS = 2 * 2 * 128 * PS * 4;        // 81.9 KB
    const int SMC = (128 * PO + 64 * PZ) * 4;    // 69.6 KB

    static bool attr_done = false;
    if (!attr_done) {
        cudaFuncSetAttribute(fusedA,   cudaFuncAttributeMaxDynamicSharedMemorySize, SMA);
        cudaFuncSetAttribute(syrk_mma, cudaFuncAttributeMaxDynamicSharedMemorySize, SMS);
        cudaFuncSetAttribute(fusedC,   cudaFuncAttributeMaxDynamicSharedMemorySize, SMC);
        attr_done = true;
    }

    prep_w<<<64, 512>>>(a_w, ag_w, g_wp, o_w);
    fusedA<<<LL / 64, 256, SMA>>>(z, norm_g, norm_b, a_b, ag_b, g_bp);
    syrk_mma<<<dim3(10, 128), 256, SMS>>>();
    fusedC<<<dim3(8, L), 256, SMC>>>(onorm_g, onorm_b, o_b, out);
}

// round 11
// speedup vs baseline: 1.5462x; 1.0566x over previous
#include <cuda_runtime.h>
#include <cuda_fp16.h>
#include <math.h>
#include <stdint.h>

#define L 512
#define LL (L*L)
#define PZ 136   // tf32 tile pitch in words (mod 32 == 8 -> conflict-free uint2 frags)
#define PO 68    // fusedC gather tile pitch (floats)
#define PH 72    // fusedA fp16 staging pitch in HALVES (144B, 16B-aligned)
#define PS 40    // syrk chunk pitch in WORDS (80 halves per row slot, 64 used)

// ---- scratch (device globals; allocation-free contract) ----
__device__ __half   g_gate[(size_t)LL*128]; // frag-major __half2 layout
__device__ __half   g_at  [(size_t)128*LL]; // gated a, fp16, l-dim pair-permuted
__device__ __half   g_o   [(size_t)128*LL]; // einsum output, fp16
__device__ uint32_t g_awt [128*128];        // tf32 weights, fragment-major
__device__ uint32_t g_agwt[128*128];
__device__ uint32_t g_gwt [128*128];
__device__ uint32_t g_owt [128*128];

__device__ __forceinline__ float sigmoidf_(float x) { return 1.0f / (1.0f + expf(-x)); }

__device__ __forceinline__ uint32_t f2tf(float f) {
    uint32_t u;
    asm("cvt.rna.tf32.f32 %0, %1;" : "=r"(u) : "f"(f));
    return u;
}

// tf32 k8 permutation (order 0,4,1,5,2,6,3,7) — used in fusedC smem only
__device__ __forceinline__ int kperm(int k) {
    return (k & ~7) | (((k & 3) << 1) | ((k >> 2) & 1));
}

// fp16 k16 pair permutation: [k0,k1,k8,k9,k2,k3,k10,k11,k4,k5,k12,k13,k6,k7,k14,k15]
__device__ __forceinline__ int p16(int k) {
    return (k & ~15) | (((k >> 1) & 3) << 2) | (((k >> 3) & 1) << 1) | (k & 1);
}

// frag-major __half2 index for gate[(row, col even pair)]
__device__ __forceinline__ size_t gate_fi(size_t row, int col) {
    return ((row >> 4) * 16 + (size_t)(col >> 3)) * 64 +
           ((row >> 3) & 1) * 32 + (row & 7) * 4 + ((col & 7) >> 1);
}

__device__ __forceinline__ void mma8(float* c, const uint32_t* a, uint32_t b0, uint32_t b1) {
    asm volatile(
        "mma.sync.aligned.m16n8k8.row.col.f32.tf32.tf32.f32 "
        "{%0,%1,%2,%3}, {%4,%5,%6,%7}, {%8,%9}, {%0,%1,%2,%3};\n"
        : "+f"(c[0]), "+f"(c[1]), "+f"(c[2]), "+f"(c[3])
        : "r"(a[0]), "r"(a[1]), "r"(a[2]), "r"(a[3]), "r"(b0), "r"(b1));
}

// fp16 m16n8k16
__device__ __forceinline__ void mma16h(float* c, uint32_t a0, uint32_t a1,
                                       uint32_t a2, uint32_t a3,
                                       uint32_t b0, uint32_t b1) {
    asm volatile(
        "mma.sync.aligned.m16n8k16.row.col.f32.f16.f16.f32 "
        "{%0,%1,%2,%3}, {%4,%5,%6,%7}, {%8,%9}, {%0,%1,%2,%3};\n"
        : "+f"(c[0]), "+f"(c[1]), "+f"(c[2]), "+f"(c[3])
        : "r"(a0), "r"(a1), "r"(a2), "r"(a3), "r"(b0), "r"(b1));
}

__device__ __forceinline__ void cpa16(void* dst, const void* src) {
    uint32_t s = (uint32_t)__cvta_generic_to_shared(dst);
    asm volatile("cp.async.cg.shared.global [%0], [%1], 16;\n" :: "r"(s), "l"(src));
}
__device__ __forceinline__ void cpa_commit() { asm volatile("cp.async.commit_group;\n" ::: "memory"); }
template<int N> __device__ __forceinline__ void cpa_wait() {
    asm volatile("cp.async.wait_group %0;\n" :: "n"(N) : "memory");
}

// ============================================================
// K0: pre-convert weights to tf32, FRAGMENT-MAJOR layout
// ============================================================
__global__ void prep_w(const float* __restrict__ aw, const float* __restrict__ agw,
                       const float* __restrict__ gw, const float* __restrict__ ow) {
    int idx = blockIdx.x * 512 + threadIdx.x;   // 32768 total (4 x 8192 uint2)
    int w = idx >> 13, i = idx & 8191;
    int lane = i & 31, ks = (i >> 5) & 15, g = i >> 9;
    int lr = lane >> 2, lc = lane & 3;
    const float* src = (w == 0) ? aw : (w == 1) ? agw : (w == 2) ? gw : ow;
    uint32_t* dst = (w == 0) ? g_awt : (w == 1) ? g_agwt : (w == 2) ? g_gwt : g_owt;
    int srow = g * 8 + lr, k0 = ks * 8 + lc;
    dst[i * 2]     = f2tf(src[srow * 128 + k0]);
    dst[i * 2 + 1] = f2tf(src[srow * 128 + k0 + 4]);
}

// ============================================================
// K1: fused LN + dual GEMM (a,ag) + gating -> fp16 g_at (staged
//     via smem, pair-permuted, coalesced) + gate GEMM. 256 thr.
// ============================================================
__global__ void __launch_bounds__(256, 2)
fusedA(const float* __restrict__ z, const float* __restrict__ ng, const float* __restrict__ nb,
       const float* __restrict__ ab, const float* __restrict__ agb, const float* __restrict__ gb) {
    extern __shared__ uint32_t sm[];
    uint32_t* sZ = sm;                              // 64 * PZ tf32 zn (k-permuted)
    __half*   sP = reinterpret_cast<__half*>(sm + 64 * PZ);  // [col 128][row PH]
    const int tid = threadIdx.x;
    const int wid = tid >> 5, lane = tid & 31;
    const int lr = lane >> 2, lc = lane & 3;
    const size_t m0 = (size_t)blockIdx.x * 64;

    const uint2* WA = reinterpret_cast<const uint2*>(g_awt);
    const uint2* WQ = reinterpret_cast<const uint2*>(g_agwt);
    const uint2* WG = reinterpret_cast<const uint2*>(g_gwt);
    __half2* GATE2 = reinterpret_cast<__half2*>(g_gate);

    // LayerNorm: warp w handles rows [8w, 8w+8); write k-permuted (tf32 k8 perm)
    {
        float4 g4 = reinterpret_cast<const float4*>(ng)[lane];
        float4 b4 = reinterpret_cast<const float4*>(nb)[lane];
        const int sgrp = (lane >> 1) * 8 + (lane & 1);
#pragma unroll
        for (int it = 0; it < 8; it++) {
            int row = wid * 8 + it;
            float4 v = reinterpret_cast<const float4*>(z)[(m0 + row) * 32 + lane];
            float s = v.x + v.y + v.z + v.w;
            float q = v.x*v.x + v.y*v.y + v.z*v.z + v.w*v.w;
#pragma unroll
            for (int o = 16; o > 0; o >>= 1) {
                s += __shfl_xor_sync(0xffffffffu, s, o);
                q += __shfl_xor_sync(0xffffffffu, q, o);
            }
            float mean = s * (1.0f / 128.0f);
            float var  = q * (1.0f / 128.0f) - mean * mean;
            float rs   = rsqrtf(var + 1e-5f);
            uint32_t* d = sZ + row * PZ + sgrp;
            d[0] = f2tf((v.x - mean) * rs * g4.x + b4.x);
            d[2] = f2tf((v.y - mean) * rs * g4.y + b4.y);
            d[4] = f2tf((v.z - mean) * rs * g4.z + b4.z);
            d[6] = f2tf((v.w - mean) * rs * g4.w + b4.w);
        }
    }
    __syncthreads();

    // ---- dual GEMM: acc_a = zn@a_w^T, acc_q = zn@ag_w^T ----
    float acc_a[4][2][4], acc_q[4][2][4];
#pragma unroll
    for (int mf = 0; mf < 4; mf++)
#pragma unroll
        for (int nf = 0; nf < 2; nf++)
#pragma unroll
            for (int v = 0; v < 4; v++) { acc_a[mf][nf][v] = 0.0f; acc_q[mf][nf][v] = 0.0f; }

#pragma unroll
    for (int ks = 0; ks < 16; ks++) {
        int kb = ks * 8;
        uint32_t a[4][4];
#pragma unroll
        for (int mf = 0; mf < 4; mf++) {
            int row = mf * 16 + lr;
            uint2 lo = *reinterpret_cast<const uint2*>(sZ + row * PZ + kb + 2 * lc);
            uint2 hi = *reinterpret_cast<const uint2*>(sZ + (row + 8) * PZ + kb + 2 * lc);
            a[mf][0] = lo.x; a[mf][1] = hi.x; a[mf][2] = lo.y; a[mf][3] = hi.y;
        }
#pragma unroll
        for (int nf = 0; nf < 2; nf++) {
            int g = wid * 2 + nf;
            uint2 ba = __ldg(WA + g * 512 + ks * 32 + lane);
            uint2 bq = __ldg(WQ + g * 512 + ks * 32 + lane);
#pragma unroll
            for (int mf = 0; mf < 4; mf++) {
                mma8(acc_a[mf][nf], a[mf], ba.x, ba.y);
                mma8(acc_q[mf][nf], a[mf], bq.x, bq.y);
            }
        }
    }

    // epilogue: P = (a + ab) * sigmoid(q + agb) -> fp16 staged in sP (pair-perm rows)
#pragma unroll
    for (int nf = 0; nf < 2; nf++) {
        int col = wid * 16 + nf * 8 + 2 * lc;
        float ba0 = __ldg(ab + col),  ba1 = __ldg(ab + col + 1);
        float bq0 = __ldg(agb + col), bq1 = __ldg(agb + col + 1);
#pragma unroll
        for (int mf = 0; mf < 4; mf++) {
            int r0 = p16(mf * 16 + lr), r1 = p16(mf * 16 + 8 + lr);
            sP[col * PH + r0]       = __float2half_rn((acc_a[mf][nf][0] + ba0) * sigmoidf_(acc_q[mf][nf][0] + bq0));
            sP[(col + 1) * PH + r0] = __float2half_rn((acc_a[mf][nf][1] + ba1) * sigmoidf_(acc_q[mf][nf][1] + bq1));
            sP[col * PH + r1]       = __float2half_rn((acc_a[mf][nf][2] + ba0) * sigmoidf_(acc_q[mf][nf][2] + bq0));
            sP[(col + 1) * PH + r1] = __float2half_rn((acc_a[mf][nf][3] + ba1) * sigmoidf_(acc_q[mf][nf][3] + bq1));
        }
    }
    __syncthreads();

    // coalesced uint4 store of fp16 a-tile: 128 cols x 64 halves
#pragma unroll
    for (int e = 0; e < 4; e++) {
        int idx = tid + 256 * e;           // 1024 uint4
        int c = idx >> 3, e8 = idx & 7;    // 8 uint4 per col
        uint4 v = *reinterpret_cast<const uint4*>(sP + c * PH + e8 * 8);
        *reinterpret_cast<uint4*>(g_at + (size_t)c * LL + m0 + e8 * 8) = v;
    }

    // ---- gate GEMM (sZ unmodified) ----
    float acc_g[4][2][4];
#pragma unroll
    for (int mf = 0; mf < 4; mf++)
#pragma unroll
        for (int nf = 0; nf < 2; nf++)
#pragma unroll
            for (int v = 0; v < 4; v++) acc_g[mf][nf][v] = 0.0f;

#pragma unroll
    for (int ks = 0; ks < 16; ks++) {
        int kb = ks * 8;
        uint32_t a[4][4];
#pragma unroll
        for (int mf = 0; mf < 4; mf++) {
            int row = mf * 16 + lr;
            uint2 lo = *reinterpret_cast<const uint2*>(sZ + row * PZ + kb + 2 * lc);
            uint2 hi = *reinterpret_cast<const uint2*>(sZ + (row + 8) * PZ + kb + 2 * lc);
            a[mf][0] = lo.x; a[mf][1] = hi.x; a[mf][2] = lo.y; a[mf][3] = hi.y;
        }
#pragma unroll
        for (int nf = 0; nf < 2; nf++) {
            int g = wid * 2 + nf;
            uint2 bg = __ldg(WG + g * 512 + ks * 32 + lane);
#pragma unroll
            for (int mf = 0; mf < 4; mf++)
                mma8(acc_g[mf][nf], a[mf], bg.x, bg.y);
        }
    }

    // gate stored frag-major fp16 (coalesced __half2)
#pragma unroll
    for (int nf = 0; nf < 2; nf++) {
        int col = wid * 16 + nf * 8 + 2 * lc;
        float b0v = __ldg(gb + col), b1v = __ldg(gb + col + 1);
#pragma unroll
        for (int mf = 0; mf < 4; mf++) {
            size_t row = m0 + mf * 16 + lr;
            size_t fi = gate_fi(row, col);
            GATE2[fi]      = __floats2half2_rn(sigmoidf_(acc_g[mf][nf][0] + b0v),
                                               sigmoidf_(acc_g[mf][nf][1] + b1v));
            GATE2[fi + 32] = __floats2half2_rn(sigmoidf_(acc_g[mf][nf][2] + b0v),
                                               sigmoidf_(acc_g[mf][nf][3] + b1v));
        }
    }
}

// ============================================================
// K2: fp16 SYRK per channel (m16n8k16, fp32 accum), cp.async
//     double-buffered, k-chunk 64. fp16 output. 256 thr.
// ============================================================
__global__ void __launch_bounds__(256, 2)
syrk_mma() {
    extern __shared__ uint32_t sm[];   // 2 stages x (A + B), pitch PS words/row
    const int tid  = threadIdx.x;
    const int wid  = tid >> 5, lane = tid & 31;
    const int wm   = wid >> 1, wn = wid & 1;
    const int lr   = lane >> 2, lc = lane & 3;

    const int c = blockIdx.y;
    int rem = blockIdx.x, bi = 0, span = 4;
    while (rem >= span) { rem -= span; span--; bi++; }
    int bj = bi + rem;
    const int i0 = bi * 128, j0 = bj * 128;
    const bool diag = (bi == bj);

    const __half* __restrict__ Ag = g_at + (size_t)c * LL;
    __half* __restrict__ O = g_o + (size_t)c * LL;

    const int STG_SZ = 2 * 128 * PS;   // words per stage (A+B)

    auto load_chunk = [&](int kc, int buf) {
        uint32_t* sA = sm + buf * STG_SZ;
        uint32_t* sB = sA + 128 * PS;
#pragma unroll
        for (int e = 0; e < 4; e++) {
            int idx = tid + 256 * e;   // 1024 cpa16 per tile (128 rows x 128B)
            int r = idx >> 3, c8 = idx & 7;
            cpa16(sA + r * PS + c8 * 4, Ag + (size_t)(i0 + r) * 512 + kc * 64 + c8 * 8);
            if (!diag)
                cpa16(sB + r * PS + c8 * 4, Ag + (size_t)(j0 + r) * 512 + kc * 64 + c8 * 8);
        }
        cpa_commit();
    };

    float acc[2][8][4];
#pragma unroll
    for (int mf = 0; mf < 2; mf++)
#pragma unroll
        for (int nf = 0; nf < 8; nf++)
#pragma unroll
            for (int v = 0; v < 4; v++) acc[mf][nf][v] = 0.0f;

    load_chunk(0, 0);

    for (int kc = 0; kc < 8; kc++) {
        if (kc + 1 < 8) { load_chunk(kc + 1, (kc + 1) & 1); cpa_wait<1>(); }
        else            { cpa_wait<0>(); }
        __syncthreads();
        const uint32_t* sA = sm + (kc & 1) * STG_SZ;
        const uint32_t* sB = diag ? sA : sA + 128 * PS;
#pragma unroll
        for (int g = 0; g < 4; g++) {       // 4 k16-groups per chunk
            int kb = g * 8;                 // word offset
            uint32_t a[2][4];
#pragma unroll
            for (int mf = 0; mf < 2; mf++) {
                int row = wm * 32 + mf * 16 + lr;
                uint2 lo = *reinterpret_cast<const uint2*>(sA + row * PS + kb + 2 * lc);
                uint2 hi = *reinterpret_cast<const uint2*>(sA + (row + 8) * PS + kb + 2 * lc);
                a[mf][0] = lo.x; a[mf][1] = hi.x; a[mf][2] = lo.y; a[mf][3] = hi.y;
            }
#pragma unroll
            for (int nf = 0; nf < 8; nf++) {
                int col = wn * 64 + nf * 8 + lr;
                uint2 b = *reinterpret_cast<const uint2*>(sB + col * PS + kb + 2 * lc);
                mma16h(acc[0][nf], a[0][0], a[0][1], a[0][2], a[0][3], b.x, b.y);
                mma16h(acc[1][nf], a[1][0], a[1][1], a[1][2], a[1][3], b.x, b.y);
            }
        }
        __syncthreads();
    }

    // direct tile write (fp16 __half2)
#pragma unroll
    for (int mf = 0; mf < 2; mf++) {
#pragma unroll
        for (int nf = 0; nf < 8; nf++) {
            int rowi = i0 + wm * 32 + mf * 16 + lr;
            int colj = j0 + wn * 64 + nf * 8 + 2 * lc;
            *reinterpret_cast<__half2*>(O + (size_t)rowi * 512 + colj) =
                __floats2half2_rn(acc[mf][nf][0], acc[mf][nf][1]);
            *reinterpret_cast<__half2*>(O + (size_t)(rowi + 8) * 512 + colj) =
                __floats2half2_rn(acc[mf][nf][2], acc[mf][nf][3]);
        }
    }

    // mirror: scalar half stores (8 consecutive rows per quarter-warp column)
    if (!diag) {
#pragma unroll
        for (int mf = 0; mf < 2; mf++) {
#pragma unroll
            for (int nf = 0; nf < 8; nf++) {
                int r  = wm * 32 + mf * 16 + lr;
                int cA = wn * 64 + nf * 8 + 2 * lc;
                O[(size_t)(j0 + cA) * 512 + i0 + r]         = __float2half_rn(acc[mf][nf][0]);
                O[(size_t)(j0 + cA + 1) * 512 + i0 + r]     = __float2half_rn(acc[mf][nf][1]);
                O[(size_t)(j0 + cA) * 512 + i0 + r + 8]     = __float2half_rn(acc[mf][nf][2]);
                O[(size_t)(j0 + cA + 1) * 512 + i0 + r + 8] = __float2half_rn(acc[mf][nf][3]);
            }
        }
    }
}

// ============================================================
// K3: fused gather (fp16 -> fp32 smem) + channel-LN + final
//     projection + fp16 gating.
// ============================================================
__global__ void __launch_bounds__(256, 3)
fusedC(const float* __restrict__ ong, const float* __restrict__ onb,
       const float* __restrict__ ob, float* __restrict__ out) {
    extern __shared__ uint32_t sm[];
    float*    sO = reinterpret_cast<float*>(sm);   // [c 128][jj 64], pitch PO
    uint32_t* sT = sm + 128 * PO;                  // [jj 64][k-perm c], pitch PZ
    __shared__ float ps[4][64], pq[4][64], mS[64], rS[64];

    const int tid = threadIdx.x;
    const int wid = tid >> 5, lane = tid & 31;
    const int wm = wid >> 2, wn = wid & 3;
    const int lr = lane >> 2, lc = lane & 3;
    const int i = blockIdx.y, j0 = blockIdx.x * 64;

    const uint2* WO = reinterpret_cast<const uint2*>(g_owt);
    const __half2* GATE2 = reinterpret_cast<const __half2*>(g_gate);

    // gather o tile [c][jj]: fp16 -> fp32 in smem
#pragma unroll
    for (int e = 0; e < 4; e++) {
        int idx = tid + 256 * e;       // 1024 uint4 (8 halves each)
        int c = idx >> 3, j8 = idx & 7;
        uint4 raw = *reinterpret_cast<const uint4*>(g_o + (size_t)c * LL + (size_t)i * 512 + j0 + j8 * 8);
        const __half2* h = reinterpret_cast<const __half2*>(&raw);
        float* d = sO + c * PO + j8 * 8;
#pragma unroll
        for (int p = 0; p < 4; p++) {
            float2 f = __half22float2(h[p]);
            d[p * 2]     = f.x;
            d[p * 2 + 1] = f.y;
        }
    }
    __syncthreads();

    // channel reduce
    {
        int col = tid & 63, qtr = tid >> 6;
        float s = 0.0f, q = 0.0f;
#pragma unroll 8
        for (int c = qtr * 32; c < qtr * 32 + 32; c++) {
            float v = sO[c * PO + col];
            s += v; q += v * v;
        }
        ps[qtr][col] = s; pq[qtr][col] = q;
    }
    __syncthreads();
    if (tid < 64) {
        float ss = ps[0][tid] + ps[1][tid] + ps[2][tid] + ps[3][tid];
        float qq = pq[0][tid] + pq[1][tid] + pq[2][tid] + pq[3][tid];
        float mean = ss * (1.0f / 128.0f);
        float var  = qq * (1.0f / 128.0f) - mean * mean;
        mS[tid] = mean;
        rS[tid] = rsqrtf(var + 1e-5f);
    }
    __syncthreads();

    // normalize -> transposed + k-permuted tf32 in sT
    {
        const int warp = wid;
#pragma unroll 8
        for (int e = 0; e < 32; e++) {
            int gidx = e * 8 + warp;
            int c = (gidx & 15) * 8 + (lane & 7);
            int jj = (gidx >> 4) * 4 + (lane >> 3);
            float v = (sO[c * PO + jj] - mS[jj]) * rS[jj] * __ldg(ong + c) + __ldg(onb + c);
            sT[jj * PZ + kperm(c)] = f2tf(v);
        }
    }
    __syncthreads();

    // GEMM: rows = jj, K = c, B frag-major L1
    float acc[2][4][4];
#pragma unroll
    for (int mf = 0; mf < 2; mf++)
#pragma unroll
        for (int nf = 0; nf < 4; nf++)
#pragma unroll
            for (int v = 0; v < 4; v++) acc[mf][nf][v] = 0.0f;

#pragma unroll
    for (int ks = 0; ks < 16; ks++) {
        int kb = ks * 8;
        uint32_t a[2][4];
#pragma unroll
        for (int mf = 0; mf < 2; mf++) {
            int row = wm * 32 + mf * 16 + lr;
            uint2 lo = *reinterpret_cast<const uint2*>(sT + row * PZ + kb + 2 * lc);
            uint2 hi = *reinterpret_cast<const uint2*>(sT + (row + 8) * PZ + kb + 2 * lc);
            a[mf][0] = lo.x; a[mf][1] = hi.x; a[mf][2] = lo.y; a[mf][3] = hi.y;
        }
#pragma unroll
        for (int nf = 0; nf < 4; nf++) {
            int g = wn * 4 + nf;
            uint2 b = __ldg(WO + g * 512 + ks * 32 + lane);
            mma8(acc[0][nf], a[0], b.x, b.y);
            mma8(acc[1][nf], a[1], b.x, b.y);
        }
    }
    __syncthreads();   // reuse sT as output stage

    // epilogue: bias + fp16 gate (frag-major), stage into sT
    const size_t grow = (size_t)i * 512 + j0;
    float* sR = reinterpret_cast<float*>(sT);
#pragma unroll
    for (int mf = 0; mf < 2; mf++) {
#pragma unroll
        for (int nf = 0; nf < 4; nf++) {
            int jj = wm * 32 + mf * 16 + lr;
            int col = wn * 32 + nf * 8 + 2 * lc;
            float b0v = __ldg(ob + col), b1v = __ldg(ob + col + 1);
            size_t fi = gate_fi(grow + jj, col);
            float2 gt0 = __half22float2(GATE2[fi]);
            float2 gt1 = __half22float2(GATE2[fi + 32]);
            *reinterpret_cast<float2*>(sR + jj * PZ + col) =
                make_float2((acc[mf][nf][0] + b0v) * gt0.x, (acc[mf][nf][1] + b1v) * gt0.y);
            *reinterpret_cast<float2*>(sR + (jj + 8) * PZ + col) =
                make_float2((acc[mf][nf][2] + b0v) * gt1.x, (acc[mf][nf][3] + b1v) * gt1.y);
        }
    }
    __syncthreads();

    // coalesced output store
#pragma unroll 4
    for (int e = 0; e < 16; e++) {
        int idx = tid + 256 * e;
        int jj = idx >> 6, c2 = idx & 63;
        float2 v = *reinterpret_cast<const float2*>(sR + jj * PZ + 2 * c2);
        *reinterpret_cast<float2*>(out + (grow + jj) * 128 + 2 * c2) = v;
    }
}

// ============================================================
// launch
// ============================================================
extern "C" void kernel_launch(void* const* d_in, const int* in_sizes, int n_in,
                              void* d_out, int out_size) {
    const float* z      = (const float*)d_in[0];
    const float* norm_g = (const float*)d_in[1];
    const float* norm_b = (const float*)d_in[2];
    const float* a_w    = (const float*)d_in[3];
    const float* a_b    = (const float*)d_in[4];
    const float* ag_w   = (const float*)d_in[5];
    const float* ag_b   = (const float*)d_in[6];
    const float* onorm_g= (const float*)d_in[7];
    const float* onorm_b= (const float*)d_in[8];
    const float* o_w    = (const float*)d_in[9];
    const float* o_b    = (const float*)d_in[10];
    const float* g_wp   = (const float*)d_in[11];
    const float* g_bp   = (const float*)d_in[12];
    float* out = (float*)d_out;

    const int SMA = 64 * PZ * 4 + 128 * PH * 2;  // 52.9 KB
    const int SMS = 2 * 2 * 128 * PS * 4;        // 81.9 KB
    const int SMC = (128 * PO + 64 * PZ) * 4;    // 69.6 KB

    static bool attr_done = false;
    if (!attr_done) {
        cudaFuncSetAttribute(fusedA,   cudaFuncAttributeMaxDynamicSharedMemorySize, SMA);
        cudaFuncSetAttribute(syrk_mma, cudaFuncAttributeMaxDynamicSharedMemorySize, SMS);
        cudaFuncSetAttribute(fusedC,   cudaFuncAttributeMaxDynamicSharedMemorySize, SMC);
        attr_done = true;
    }

    prep_w<<<64, 512>>>(a_w, ag_w, g_wp, o_w);
    fusedA<<<LL / 64, 256, SMA>>>(z, norm_g, norm_b, a_b, ag_b, g_bp);
    syrk_mma<<<dim3(10, 128), 256, SMS>>>();
    fusedC<<<dim3(8, L), 256, SMC>>>(onorm_g, onorm_b, o_b, out);
}

// round 12
// speedup vs baseline: 1.9306x; 1.2486x over previous
#include <cuda_runtime.h>
#include <cuda_fp16.h>
#include <math.h>
#include <stdint.h>

#define L 512
#define LL (L*L)
#define PO 68    // fusedC gather tile pitch (floats)
#define PW 72    // fp16 tile pitch in WORDS (144 halves; 72 mod 32 == 8)
#define PH 72    // fusedA fp16 staging pitch in HALVES (144B, 16B-aligned)
#define PS 40    // syrk chunk pitch in WORDS (80 halves per row slot, 64 used)
#define PR 136   // fusedC fp32 result staging pitch (floats)

// ---- scratch (device globals; allocation-free contract) ----
__device__ __half   g_gate[(size_t)LL*128]; // frag-major __half2 layout
__device__ __half   g_at  [(size_t)128*LL]; // gated a, fp16, l-dim pair-permuted
__device__ __half   g_o   [(size_t)128*LL]; // einsum output, fp16
__device__ uint32_t g_awh [8192];           // fp16 weights, frag-major (uint2=4 halves)
__device__ uint32_t g_agwh[8192];
__device__ uint32_t g_gwh [8192];
__device__ uint32_t g_owh [8192];

__device__ __forceinline__ float sigmoidf_(float x) { return 1.0f / (1.0f + expf(-x)); }

// pair/k8 permutation (order 0,4,1,5,2,6,3,7)
__device__ __forceinline__ int kperm(int k) {
    return (k & ~7) | (((k & 3) << 1) | ((k >> 2) & 1));
}
// fp16 k16 pair permutation on halves
__device__ __forceinline__ int p16(int k) {
    return (k & ~15) | (((k >> 1) & 3) << 2) | (((k >> 3) & 1) << 1) | (k & 1);
}
// frag-major __half2 index for gate[(row, col even pair)]
__device__ __forceinline__ size_t gate_fi(size_t row, int col) {
    return ((row >> 4) * 16 + (size_t)(col >> 3)) * 64 +
           ((row >> 3) & 1) * 32 + (row & 7) * 4 + ((col & 7) >> 1);
}

// fp16 m16n8k16, fp32 accum
__device__ __forceinline__ void mma16h(float* c, uint32_t a0, uint32_t a1,
                                       uint32_t a2, uint32_t a3,
                                       uint32_t b0, uint32_t b1) {
    asm volatile(
        "mma.sync.aligned.m16n8k16.row.col.f32.f16.f16.f32 "
        "{%0,%1,%2,%3}, {%4,%5,%6,%7}, {%8,%9}, {%0,%1,%2,%3};\n"
        : "+f"(c[0]), "+f"(c[1]), "+f"(c[2]), "+f"(c[3])
        : "r"(a0), "r"(a1), "r"(a2), "r"(a3), "r"(b0), "r"(b1));
}

__device__ __forceinline__ void cpa16(void* dst, const void* src) {
    uint32_t s = (uint32_t)__cvta_generic_to_shared(dst);
    asm volatile("cp.async.cg.shared.global [%0], [%1], 16;\n" :: "r"(s), "l"(src));
}
__device__ __forceinline__ void cpa_commit() { asm volatile("cp.async.commit_group;\n" ::: "memory"); }
template<int N> __device__ __forceinline__ void cpa_wait() {
    asm volatile("cp.async.wait_group %0;\n" :: "n"(N) : "memory");
}

// ============================================================
// K0: pre-convert weights to fp16, FRAGMENT-MAJOR:
//     uint2 slot (g, kg, lane): halves {W[g*8+lr][16kg+2lc], +1, +8, +9}
// ============================================================
__global__ void prep_w(const float* __restrict__ aw, const float* __restrict__ agw,
                       const float* __restrict__ gw, const float* __restrict__ ow) {
    int idx = blockIdx.x * 512 + threadIdx.x;   // 16384 total (4 x 4096 uint2)
    int w = idx >> 12, i = idx & 4095;
    int lane = i & 31, kg = (i >> 5) & 7, g = i >> 8;
    int lr = lane >> 2, lc = lane & 3;
    const float* src = (w == 0) ? aw : (w == 1) ? agw : (w == 2) ? gw : ow;
    uint32_t* dst = (w == 0) ? g_awh : (w == 1) ? g_agwh : (w == 2) ? g_gwh : g_owh;
    int n = g * 8 + lr, k0 = kg * 16 + 2 * lc;
    __half2 lo = __floats2half2_rn(src[n * 128 + k0],     src[n * 128 + k0 + 1]);
    __half2 hi = __floats2half2_rn(src[n * 128 + k0 + 8], src[n * 128 + k0 + 9]);
    dst[i * 2]     = *reinterpret_cast<uint32_t*>(&lo);
    dst[i * 2 + 1] = *reinterpret_cast<uint32_t*>(&hi);
}

// ============================================================
// K1: fused LN(fp16) + dual fp16 GEMM (a,ag) + gating -> g_at
//     + fp16 gate GEMM. 256 thr, 64-row tile.
// ============================================================
__global__ void __launch_bounds__(256, 2)
fusedA(const float* __restrict__ z, const float* __restrict__ ng, const float* __restrict__ nb,
       const float* __restrict__ ab, const float* __restrict__ agb, const float* __restrict__ gb) {
    extern __shared__ uint32_t sm[];
    uint32_t* sZw = sm;                             // 64 x PW words fp16 zn (p16 layout)
    __half2*  sZ2 = reinterpret_cast<__half2*>(sm);
    __half*   sP  = reinterpret_cast<__half*>(sm + 64 * PW);  // [col 128][row PH]
    const int tid = threadIdx.x;
    const int wid = tid >> 5, lane = tid & 31;
    const int lr = lane >> 2, lc = lane & 3;
    const size_t m0 = (size_t)blockIdx.x * 64;

    const uint2* WA = reinterpret_cast<const uint2*>(g_awh);
    const uint2* WQ = reinterpret_cast<const uint2*>(g_agwh);
    const uint2* WG = reinterpret_cast<const uint2*>(g_gwh);
    __half2* GATE2 = reinterpret_cast<__half2*>(g_gate);

    // LayerNorm: warp w handles rows [8w, 8w+8); write fp16 pair-permuted
    {
        float4 g4 = reinterpret_cast<const float4*>(ng)[lane];
        float4 b4 = reinterpret_cast<const float4*>(nb)[lane];
        const int pp0 = kperm(2 * lane), pp1 = kperm(2 * lane + 1);
#pragma unroll
        for (int it = 0; it < 8; it++) {
            int row = wid * 8 + it;
            float4 v = reinterpret_cast<const float4*>(z)[(m0 + row) * 32 + lane];
            float s = v.x + v.y + v.z + v.w;
            float q = v.x*v.x + v.y*v.y + v.z*v.z + v.w*v.w;
#pragma unroll
            for (int o = 16; o > 0; o >>= 1) {
                s += __shfl_xor_sync(0xffffffffu, s, o);
                q += __shfl_xor_sync(0xffffffffu, q, o);
            }
            float mean = s * (1.0f / 128.0f);
            float var  = q * (1.0f / 128.0f) - mean * mean;
            float rs   = rsqrtf(var + 1e-5f);
            sZ2[row * PW + pp0] = __floats2half2_rn((v.x - mean) * rs * g4.x + b4.x,
                                                    (v.y - mean) * rs * g4.y + b4.y);
            sZ2[row * PW + pp1] = __floats2half2_rn((v.z - mean) * rs * g4.z + b4.z,
                                                    (v.w - mean) * rs * g4.w + b4.w);
        }
    }
    __syncthreads();

    // ---- dual fp16 GEMM: acc_a = zn@a_w^T, acc_q = zn@ag_w^T ----
    float acc_a[4][2][4], acc_q[4][2][4];
#pragma unroll
    for (int mf = 0; mf < 4; mf++)
#pragma unroll
        for (int nf = 0; nf < 2; nf++)
#pragma unroll
            for (int v = 0; v < 4; v++) { acc_a[mf][nf][v] = 0.0f; acc_q[mf][nf][v] = 0.0f; }

#pragma unroll
    for (int kg = 0; kg < 8; kg++) {
        int kb = kg * 8;
        uint32_t a[4][4];
#pragma unroll
        for (int mf = 0; mf < 4; mf++) {
            int row = mf * 16 + lr;
            uint2 lo = *reinterpret_cast<const uint2*>(sZw + row * PW + kb + 2 * lc);
            uint2 hi = *reinterpret_cast<const uint2*>(sZw + (row + 8) * PW + kb + 2 * lc);
            a[mf][0] = lo.x; a[mf][1] = hi.x; a[mf][2] = lo.y; a[mf][3] = hi.y;
        }
#pragma unroll
        for (int nf = 0; nf < 2; nf++) {
            int g = wid * 2 + nf;
            uint2 ba = __ldg(WA + g * 256 + kg * 32 + lane);
            uint2 bq = __ldg(WQ + g * 256 + kg * 32 + lane);
#pragma unroll
            for (int mf = 0; mf < 4; mf++) {
                mma16h(acc_a[mf][nf], a[mf][0], a[mf][1], a[mf][2], a[mf][3], ba.x, ba.y);
                mma16h(acc_q[mf][nf], a[mf][0], a[mf][1], a[mf][2], a[mf][3], bq.x, bq.y);
            }
        }
    }

    // epilogue: P = (a + ab) * sigmoid(q + agb) -> fp16 staged in sP (pair-perm rows)
#pragma unroll
    for (int nf = 0; nf < 2; nf++) {
        int col = wid * 16 + nf * 8 + 2 * lc;
        float ba0 = __ldg(ab + col),  ba1 = __ldg(ab + col + 1);
        float bq0 = __ldg(agb + col), bq1 = __ldg(agb + col + 1);
#pragma unroll
        for (int mf = 0; mf < 4; mf++) {
            int r0 = p16(mf * 16 + lr), r1 = p16(mf * 16 + 8 + lr);
            sP[col * PH + r0]       = __float2half_rn((acc_a[mf][nf][0] + ba0) * sigmoidf_(acc_q[mf][nf][0] + bq0));
            sP[(col + 1) * PH + r0] = __float2half_rn((acc_a[mf][nf][1] + ba1) * sigmoidf_(acc_q[mf][nf][1] + bq1));
            sP[col * PH + r1]       = __float2half_rn((acc_a[mf][nf][2] + ba0) * sigmoidf_(acc_q[mf][nf][2] + bq0));
            sP[(col + 1) * PH + r1] = __float2half_rn((acc_a[mf][nf][3] + ba1) * sigmoidf_(acc_q[mf][nf][3] + bq1));
        }
    }
    __syncthreads();

    // coalesced uint4 store of fp16 a-tile: 128 cols x 64 halves
#pragma unroll
    for (int e = 0; e < 4; e++) {
        int idx = tid + 256 * e;           // 1024 uint4
        int c = idx >> 3, e8 = idx & 7;    // 8 uint4 per col
        uint4 v = *reinterpret_cast<const uint4*>(sP + c * PH + e8 * 8);
        *reinterpret_cast<uint4*>(g_at + (size_t)c * LL + m0 + e8 * 8) = v;
    }

    // ---- fp16 gate GEMM (sZ unmodified) ----
    float acc_g[4][2][4];
#pragma unroll
    for (int mf = 0; mf < 4; mf++)
#pragma unroll
        for (int nf = 0; nf < 2; nf++)
#pragma unroll
            for (int v = 0; v < 4; v++) acc_g[mf][nf][v] = 0.0f;

#pragma unroll
    for (int kg = 0; kg < 8; kg++) {
        int kb = kg * 8;
        uint32_t a[4][4];
#pragma unroll
        for (int mf = 0; mf < 4; mf++) {
            int row = mf * 16 + lr;
            uint2 lo = *reinterpret_cast<const uint2*>(sZw + row * PW + kb + 2 * lc);
            uint2 hi = *reinterpret_cast<const uint2*>(sZw + (row + 8) * PW + kb + 2 * lc);
            a[mf][0] = lo.x; a[mf][1] = hi.x; a[mf][2] = lo.y; a[mf][3] = hi.y;
        }
#pragma unroll
        for (int nf = 0; nf < 2; nf++) {
            int g = wid * 2 + nf;
            uint2 bg = __ldg(WG + g * 256 + kg * 32 + lane);
#pragma unroll
            for (int mf = 0; mf < 4; mf++)
                mma16h(acc_g[mf][nf], a[mf][0], a[mf][1], a[mf][2], a[mf][3], bg.x, bg.y);
        }
    }

    // gate stored frag-major fp16 (coalesced __half2)
#pragma unroll
    for (int nf = 0; nf < 2; nf++) {
        int col = wid * 16 + nf * 8 + 2 * lc;
        float b0v = __ldg(gb + col), b1v = __ldg(gb + col + 1);
#pragma unroll
        for (int mf = 0; mf < 4; mf++) {
            size_t row = m0 + mf * 16 + lr;
            size_t fi = gate_fi(row, col);
            GATE2[fi]      = __floats2half2_rn(sigmoidf_(acc_g[mf][nf][0] + b0v),
                                               sigmoidf_(acc_g[mf][nf][1] + b1v));
            GATE2[fi + 32] = __floats2half2_rn(sigmoidf_(acc_g[mf][nf][2] + b0v),
                                               sigmoidf_(acc_g[mf][nf][3] + b1v));
        }
    }
}

// ============================================================
// K2: fp16 SYRK per channel (m16n8k16, fp32 accum), cp.async
//     double-buffered, k-chunk 64. fp16 output, mirror staged
//     through smem for coalesced stores. 256 thr.
// ============================================================
__global__ void __launch_bounds__(256, 2)
syrk_mma() {
    extern __shared__ uint32_t sm[];   // 2 stages x (A + B), pitch PS words/row
    const int tid  = threadIdx.x;
    const int wid  = tid >> 5, lane = tid & 31;
    const int wm   = wid >> 1, wn = wid & 1;
    const int lr   = lane >> 2, lc = lane & 3;

    const int c = blockIdx.y;
    int rem = blockIdx.x, bi = 0, span = 4;
    while (rem >= span) { rem -= span; span--; bi++; }
    int bj = bi + rem;
    const int i0 = bi * 128, j0 = bj * 128;
    const bool diag = (bi == bj);

    const __half* __restrict__ Ag = g_at + (size_t)c * LL;
    __half* __restrict__ O = g_o + (size_t)c * LL;

    const int STG_SZ = 2 * 128 * PS;   // words per stage (A+B)

    auto load_chunk = [&](int kc, int buf) {
        uint32_t* sA = sm + buf * STG_SZ;
        uint32_t* sB = sA + 128 * PS;
#pragma unroll
        for (int e = 0; e < 4; e++) {
            int idx = tid + 256 * e;
            int r = idx >> 3, c8 = idx & 7;
            cpa16(sA + r * PS + c8 * 4, Ag + (size_t)(i0 + r) * 512 + kc * 64 + c8 * 8);
            if (!diag)
                cpa16(sB + r * PS + c8 * 4, Ag + (size_t)(j0 + r) * 512 + kc * 64 + c8 * 8);
        }
        cpa_commit();
    };

    float acc[2][8][4];
#pragma unroll
    for (int mf = 0; mf < 2; mf++)
#pragma unroll
        for (int nf = 0; nf < 8; nf++)
#pragma unroll
            for (int v = 0; v < 4; v++) acc[mf][nf][v] = 0.0f;

    load_chunk(0, 0);

    for (int kc = 0; kc < 8; kc++) {
        if (kc + 1 < 8) { load_chunk(kc + 1, (kc + 1) & 1); cpa_wait<1>(); }
        else            { cpa_wait<0>(); }
        __syncthreads();
        const uint32_t* sA = sm + (kc & 1) * STG_SZ;
        const uint32_t* sB = diag ? sA : sA + 128 * PS;
#pragma unroll
        for (int g = 0; g < 4; g++) {
            int kb = g * 8;
            uint32_t a[2][4];
#pragma unroll
            for (int mf = 0; mf < 2; mf++) {
                int row = wm * 32 + mf * 16 + lr;
                uint2 lo = *reinterpret_cast<const uint2*>(sA + row * PS + kb + 2 * lc);
                uint2 hi = *reinterpret_cast<const uint2*>(sA + (row + 8) * PS + kb + 2 * lc);
                a[mf][0] = lo.x; a[mf][1] = hi.x; a[mf][2] = lo.y; a[mf][3] = hi.y;
            }
#pragma unroll
            for (int nf = 0; nf < 8; nf++) {
                int col = wn * 64 + nf * 8 + lr;
                uint2 b = *reinterpret_cast<const uint2*>(sB + col * PS + kb + 2 * lc);
                mma16h(acc[0][nf], a[0][0], a[0][1], a[0][2], a[0][3], b.x, b.y);
                mma16h(acc[1][nf], a[1][0], a[1][1], a[1][2], a[1][3], b.x, b.y);
            }
        }
        __syncthreads();
    }

    // direct tile write (fp16 __half2)
#pragma unroll
    for (int mf = 0; mf < 2; mf++) {
#pragma unroll
        for (int nf = 0; nf < 8; nf++) {
            int rowi = i0 + wm * 32 + mf * 16 + lr;
            int colj = j0 + wn * 64 + nf * 8 + 2 * lc;
            *reinterpret_cast<__half2*>(O + (size_t)rowi * 512 + colj) =
                __floats2half2_rn(acc[mf][nf][0], acc[mf][nf][1]);
            *reinterpret_cast<__half2*>(O + (size_t)(rowi + 8) * 512 + colj) =
                __floats2half2_rn(acc[mf][nf][2], acc[mf][nf][3]);
        }
    }

    // mirror: stage transposed fp16 tile in smem, then coalesced uint4 stores
    if (!diag) {
        __half* st = reinterpret_cast<__half*>(sm);   // [col 128][row], pitch 136 halves
#pragma unroll
        for (int mf = 0; mf < 2; mf++) {
#pragma unroll
            for (int nf = 0; nf < 8; nf++) {
                int r  = wm * 32 + mf * 16 + lr;
                int cA = wn * 64 + nf * 8 + 2 * lc;
                st[cA * 136 + r]           = __float2half_rn(acc[mf][nf][0]);
                st[(cA + 1) * 136 + r]     = __float2half_rn(acc[mf][nf][1]);
                st[cA * 136 + r + 8]       = __float2half_rn(acc[mf][nf][2]);
                st[(cA + 1) * 136 + r + 8] = __float2half_rn(acc[mf][nf][3]);
            }
        }
        __syncthreads();
#pragma unroll
        for (int e = 0; e < 8; e++) {
            int idx = tid + 256 * e;        // 2048 uint4
            int col = idx >> 4, e8 = idx & 15;
            uint4 v = *reinterpret_cast<const uint4*>(st + col * 136 + e8 * 8);
            *reinterpret_cast<uint4*>(O + (size_t)(j0 + col) * 512 + i0 + e8 * 8) = v;
        }
    }
}

// ============================================================
// K3: fused gather (fp16 -> fp32 smem) + channel-LN + fp16
//     projection + fp16 gating.
// ============================================================
__global__ void __launch_bounds__(256, 3)
fusedC(const float* __restrict__ ong, const float* __restrict__ onb,
       const float* __restrict__ ob, float* __restrict__ out) {
    extern __shared__ uint32_t sm[];
    float*    sO  = reinterpret_cast<float*>(sm);   // [c 128][jj 64], pitch PO
    uint32_t* sTw = sm + 128 * PO;                  // fp16 [jj 64][p16 c], pitch PW words
    __half*   sTh = reinterpret_cast<__half*>(sTw);
    __shared__ float ps[4][64], pq[4][64], mS[64], rS[64];

    const int tid = threadIdx.x;
    const int wid = tid >> 5, lane = tid & 31;
    const int wm = wid >> 2, wn = wid & 3;
    const int lr = lane >> 2, lc = lane & 3;
    const int i = blockIdx.y, j0 = blockIdx.x * 64;

    const uint2* WO = reinterpret_cast<const uint2*>(g_owh);
    const __half2* GATE2 = reinterpret_cast<const __half2*>(g_gate);

    // gather o tile [c][jj]: fp16 -> fp32 in smem
#pragma unroll
    for (int e = 0; e < 4; e++) {
        int idx = tid + 256 * e;       // 1024 uint4 (8 halves each)
        int c = idx >> 3, j8 = idx & 7;
        uint4 raw = *reinterpret_cast<const uint4*>(g_o + (size_t)c * LL + (size_t)i * 512 + j0 + j8 * 8);
        const __half2* h = reinterpret_cast<const __half2*>(&raw);
        float* d = sO + c * PO + j8 * 8;
#pragma unroll
        for (int p = 0; p < 4; p++) {
            float2 f = __half22float2(h[p]);
            d[p * 2]     = f.x;
            d[p * 2 + 1] = f.y;
        }
    }
    __syncthreads();

    // channel reduce
    {
        int col = tid & 63, qtr = tid >> 6;
        float s = 0.0f, q = 0.0f;
#pragma unroll 8
        for (int c = qtr * 32; c < qtr * 32 + 32; c++) {
            float v = sO[c * PO + col];
            s += v; q += v * v;
        }
        ps[qtr][col] = s; pq[qtr][col] = q;
    }
    __syncthreads();
    if (tid < 64) {
        float ss = ps[0][tid] + ps[1][tid] + ps[2][tid] + ps[3][tid];
        float qq = pq[0][tid] + pq[1][tid] + pq[2][tid] + pq[3][tid];
        float mean = ss * (1.0f / 128.0f);
        float var  = qq * (1.0f / 128.0f) - mean * mean;
        mS[tid] = mean;
        rS[tid] = rsqrtf(var + 1e-5f);
    }
    __syncthreads();

    // normalize -> transposed + p16-permuted fp16 in sT
    {
        const int warp = wid;
#pragma unroll 8
        for (int e = 0; e < 32; e++) {
            int gidx = e * 8 + warp;
            int c = (gidx & 15) * 8 + (lane & 7);
            int jj = (gidx >> 4) * 4 + (lane >> 3);
            float v = (sO[c * PO + jj] - mS[jj]) * rS[jj] * __ldg(ong + c) + __ldg(onb + c);
            sTh[jj * (2 * PW) + p16(c)] = __float2half_rn(v);
        }
    }
    __syncthreads();

    // fp16 GEMM: rows = jj, K = c, B frag-major L1
    float acc[2][4][4];
#pragma unroll
    for (int mf = 0; mf < 2; mf++)
#pragma unroll
        for (int nf = 0; nf < 4; nf++)
#pragma unroll
            for (int v = 0; v < 4; v++) acc[mf][nf][v] = 0.0f;

#pragma unroll
    for (int kg = 0; kg < 8; kg++) {
        int kb = kg * 8;
        uint32_t a[2][4];
#pragma unroll
        for (int mf = 0; mf < 2; mf++) {
            int row = wm * 32 + mf * 16 + lr;
            uint2 lo = *reinterpret_cast<const uint2*>(sTw + row * PW + kb + 2 * lc);
            uint2 hi = *reinterpret_cast<const uint2*>(sTw + (row + 8) * PW + kb + 2 * lc);
            a[mf][0] = lo.x; a[mf][1] = hi.x; a[mf][2] = lo.y; a[mf][3] = hi.y;
        }
#pragma unroll
        for (int nf = 0; nf < 4; nf++) {
            int g = wn * 4 + nf;
            uint2 b = __ldg(WO + g * 256 + kg * 32 + lane);
            mma16h(acc[0][nf], a[0][0], a[0][1], a[0][2], a[0][3], b.x, b.y);
            mma16h(acc[1][nf], a[1][0], a[1][1], a[1][2], a[1][3], b.x, b.y);
        }
    }
    __syncthreads();   // reuse sT region as fp32 output stage

    // epilogue: bias + fp16 gate (frag-major), stage fp32 into sR
    const size_t grow = (size_t)i * 512 + j0;
    float* sR = reinterpret_cast<float*>(sTw);      // pitch PR floats
#pragma unroll
    for (int mf = 0; mf < 2; mf++) {
#pragma unroll
        for (int nf = 0; nf < 4; nf++) {
            int jj = wm * 32 + mf * 16 + lr;
            int col = wn * 32 + nf * 8 + 2 * lc;
            float b0v = __ldg(ob + col), b1v = __ldg(ob + col + 1);
            size_t fi = gate_fi(grow + jj, col);
            float2 gt0 = __half22float2(GATE2[fi]);
            float2 gt1 = __half22float2(GATE2[fi + 32]);
            *reinterpret_cast<float2*>(sR + jj * PR + col) =
                make_float2((acc[mf][nf][0] + b0v) * gt0.x, (acc[mf][nf][1] + b1v) * gt0.y);
            *reinterpret_cast<float2*>(sR + (jj + 8) * PR + col) =
                make_float2((acc[mf][nf][2] + b0v) * gt1.x, (acc[mf][nf][3] + b1v) * gt1.y);
        }
    }
    __syncthreads();

    // coalesced output store
#pragma unroll 4
    for (int e = 0; e < 16; e++) {
        int idx = tid + 256 * e;
        int jj = idx >> 6, c2 = idx & 63;
        float2 v = *reinterpret_cast<const float2*>(sR + jj * PR + 2 * c2);
        *reinterpret_cast<float2*>(out + (grow + jj) * 128 + 2 * c2) = v;
    }
}

// ============================================================
// launch
// ============================================================
extern "C" void kernel_launch(void* const* d_in, const int* in_sizes, int n_in,
                              void* d_out, int out_size) {
    const float* z      = (const float*)d_in[0];
    const float* norm_g = (const float*)d_in[1];
    const float* norm_b = (const float*)d_in[2];
    const float* a_w    = (const float*)d_in[3];
    const float* a_b    = (const float*)d_in[4];
    const float* ag_w   = (const float*)d_in[5];
    const float* ag_b   = (const float*)d_in[6];
    const float* onorm_g= (const float*)d_in[7];
    const float* onorm_b= (const float*)d_in[8];
    const float* o_w    = (const float*)d_in[9];
    const float* o_b    = (const float*)d_in[10];
    const float* g_wp   = (const float*)d_in[11];
    const float* g_bp   = (const float*)d_in[12];
    float* out = (float*)d_out;

    const int SMA = 64 * PW * 4 + 128 * PH * 2;  // 36.9 KB
    const int SMS = 2 * 2 * 128 * PS * 4;        // 81.9 KB
    const int SMC = (128 * PO + 64 * PR) * 4;    // 69.6 KB

    static bool attr_done = false;
    if (!attr_done) {
        cudaFuncSetAttribute(fusedA,   cudaFuncAttributeMaxDynamicSharedMemorySize, SMA);
        cudaFuncSetAttribute(syrk_mma, cudaFuncAttributeMaxDynamicSharedMemorySize, SMS);
        cudaFuncSetAttribute(fusedC,   cudaFuncAttributeMaxDynamicSharedMemorySize, SMC);
        attr_done = true;
    }

    prep_w<<<32, 512>>>(a_w, ag_w, g_wp, o_w);
    fusedA<<<LL / 64, 256, SMA>>>(z, norm_g, norm_b, a_b, ag_b, g_bp);
    syrk_mma<<<dim3(10, 128), 256, SMS>>>();
    fusedC<<<dim3(8, L), 256, SMC>>>(onorm_g, onorm_b, o_b, out);
}

// round 14
// speedup vs baseline: 2.0014x; 1.0367x over previous
#include <cuda_runtime.h>
#include <cuda_fp16.h>
#include <math.h>
#include <stdint.h>

#define L 512
#define LL (L*L)
#define POH 72   // fusedC fp16 gather pitch in HALVES (144B)
#define PW 72    // fp16 tile pitch in WORDS (144 halves; 72 mod 32 == 8)
#define PH 72    // fusedA fp16 staging pitch in HALVES (144B, 16B-aligned)
#define PS 40    // syrk chunk pitch in WORDS (80 halves per row slot, 64 used)
#define PR 136   // fusedC fp32 result staging pitch (floats)

// ---- scratch (device globals; allocation-free contract) ----
__device__ __half   g_gate[(size_t)LL*128]; // frag-major __half2 layout
__device__ __half   g_at  [(size_t)128*LL]; // gated a, fp16, l-dim pair-permuted
__device__ __half   g_o   [(size_t)128*LL]; // einsum output, fp16
__device__ uint32_t g_awh [8192];           // fp16 weights, frag-major (uint2=4 halves)
__device__ uint32_t g_agwh[8192];
__device__ uint32_t g_gwh [8192];
__device__ uint32_t g_owh [8192];

__device__ __forceinline__ float sigmoidf_(float x) { return 1.0f / (1.0f + expf(-x)); }

// pair/k8 permutation (order 0,4,1,5,2,6,3,7)
__device__ __forceinline__ int kperm(int k) {
    return (k & ~7) | (((k & 3) << 1) | ((k >> 2) & 1));
}
// fp16 k16 pair permutation on halves
__device__ __forceinline__ int p16(int k) {
    return (k & ~15) | (((k >> 1) & 3) << 2) | (((k >> 3) & 1) << 1) | (k & 1);
}
// frag-major __half2 index for gate[(row, col even pair)]
__device__ __forceinline__ size_t gate_fi(size_t row, int col) {
    return ((row >> 4) * 16 + (size_t)(col >> 3)) * 64 +
           ((row >> 3) & 1) * 32 + (row & 7) * 4 + ((col & 7) >> 1);
}

// fp16 m16n8k16, fp32 accum
__device__ __forceinline__ void mma16h(float* c, uint32_t a0, uint32_t a1,
                                       uint32_t a2, uint32_t a3,
                                       uint32_t b0, uint32_t b1) {
    asm volatile(
        "mma.sync.aligned.m16n8k16.row.col.f32.f16.f16.f32 "
        "{%0,%1,%2,%3}, {%4,%5,%6,%7}, {%8,%9}, {%0,%1,%2,%3};\n"
        : "+f"(c[0]), "+f"(c[1]), "+f"(c[2]), "+f"(c[3])
        : "r"(a0), "r"(a1), "r"(a2), "r"(a3), "r"(b0), "r"(b1));
}

__device__ __forceinline__ void cpa16(void* dst, const void* src) {
    uint32_t s = (uint32_t)__cvta_generic_to_shared(dst);
    asm volatile("cp.async.cg.shared.global [%0], [%1], 16;\n" :: "r"(s), "l"(src));
}
__device__ __forceinline__ void cpa_commit() { asm volatile("cp.async.commit_group;\n" ::: "memory"); }
template<int N> __device__ __forceinline__ void cpa_wait() {
    asm volatile("cp.async.wait_group %0;\n" :: "n"(N) : "memory");
}

// ============================================================
// K0: pre-convert weights to fp16, FRAGMENT-MAJOR
// ============================================================
__global__ void prep_w(const float* __restrict__ aw, const float* __restrict__ agw,
                       const float* __restrict__ gw, const float* __restrict__ ow) {
    int idx = blockIdx.x * 512 + threadIdx.x;   // 16384 total (4 x 4096 uint2)
    int w = idx >> 12, i = idx & 4095;
    int lane = i & 31, kg = (i >> 5) & 7, g = i >> 8;
    int lr = lane >> 2, lc = lane & 3;
    const float* src = (w == 0) ? aw : (w == 1) ? agw : (w == 2) ? gw : ow;
    uint32_t* dst = (w == 0) ? g_awh : (w == 1) ? g_agwh : (w == 2) ? g_gwh : g_owh;
    int n = g * 8 + lr, k0 = kg * 16 + 2 * lc;
    __half2 lo = __floats2half2_rn(src[n * 128 + k0],     src[n * 128 + k0 + 1]);
    __half2 hi = __floats2half2_rn(src[n * 128 + k0 + 8], src[n * 128 + k0 + 9]);
    dst[i * 2]     = *reinterpret_cast<uint32_t*>(&lo);
    dst[i * 2 + 1] = *reinterpret_cast<uint32_t*>(&hi);
}

// ============================================================
// K1: fused LN(fp16) + dual fp16 GEMM (a,ag) + gating -> g_at
//     + fp16 gate GEMM. 256 thr, 64-row tile.
// ============================================================
__global__ void __launch_bounds__(256, 2)
fusedA(const float* __restrict__ z, const float* __restrict__ ng, const float* __restrict__ nb,
       const float* __restrict__ ab, const float* __restrict__ agb, const float* __restrict__ gb) {
    extern __shared__ uint32_t sm[];
    uint32_t* sZw = sm;                             // 64 x PW words fp16 zn (p16 layout)
    __half2*  sZ2 = reinterpret_cast<__half2*>(sm);
    __half*   sP  = reinterpret_cast<__half*>(sm + 64 * PW);  // [col 128][row PH]
    const int tid = threadIdx.x;
    const int wid = tid >> 5, lane = tid & 31;
    const int lr = lane >> 2, lc = lane & 3;
    const size_t m0 = (size_t)blockIdx.x * 64;

    const uint2* WA = reinterpret_cast<const uint2*>(g_awh);
    const uint2* WQ = reinterpret_cast<const uint2*>(g_agwh);
    const uint2* WG = reinterpret_cast<const uint2*>(g_gwh);
    __half2* GATE2 = reinterpret_cast<__half2*>(g_gate);

    // LayerNorm: warp w handles rows [8w, 8w+8); z loads batched 4-at-a-time (MLP)
    {
        float4 g4 = reinterpret_cast<const float4*>(ng)[lane];
        float4 b4 = reinterpret_cast<const float4*>(nb)[lane];
        const int pp0 = kperm(2 * lane), pp1 = kperm(2 * lane + 1);
#pragma unroll
        for (int hb = 0; hb < 2; hb++) {
            float4 vb[4];
#pragma unroll
            for (int it = 0; it < 4; it++)
                vb[it] = reinterpret_cast<const float4*>(z)[(m0 + wid * 8 + hb * 4 + it) * 32 + lane];
#pragma unroll
            for (int it = 0; it < 4; it++) {
                int row = wid * 8 + hb * 4 + it;
                float4 v = vb[it];
                float s = v.x + v.y + v.z + v.w;
                float q = v.x*v.x + v.y*v.y + v.z*v.z + v.w*v.w;
#pragma unroll
                for (int o = 16; o > 0; o >>= 1) {
                    s += __shfl_xor_sync(0xffffffffu, s, o);
                    q += __shfl_xor_sync(0xffffffffu, q, o);
                }
                float mean = s * (1.0f / 128.0f);
                float var  = q * (1.0f / 128.0f) - mean * mean;
                float rs   = rsqrtf(var + 1e-5f);
                sZ2[row * PW + pp0] = __floats2half2_rn((v.x - mean) * rs * g4.x + b4.x,
                                                        (v.y - mean) * rs * g4.y + b4.y);
                sZ2[row * PW + pp1] = __floats2half2_rn((v.z - mean) * rs * g4.z + b4.z,
                                                        (v.w - mean) * rs * g4.w + b4.w);
            }
        }
    }
    __syncthreads();

    // ---- dual fp16 GEMM: acc_a = zn@a_w^T, acc_q = zn@ag_w^T ----
    float acc_a[4][2][4], acc_q[4][2][4];
#pragma unroll
    for (int mf = 0; mf < 4; mf++)
#pragma unroll
        for (int nf = 0; nf < 2; nf++)
#pragma unroll
            for (int v = 0; v < 4; v++) { acc_a[mf][nf][v] = 0.0f; acc_q[mf][nf][v] = 0.0f; }

#pragma unroll
    for (int kg = 0; kg < 8; kg++) {
        int kb = kg * 8;
        uint32_t a[4][4];
#pragma unroll
        for (int mf = 0; mf < 4; mf++) {
            int row = mf * 16 + lr;
            uint2 lo = *reinterpret_cast<const uint2*>(sZw + row * PW + kb + 2 * lc);
            uint2 hi = *reinterpret_cast<const uint2*>(sZw + (row + 8) * PW + kb + 2 * lc);
            a[mf][0] = lo.x; a[mf][1] = hi.x; a[mf][2] = lo.y; a[mf][3] = hi.y;
        }
#pragma unroll
        for (int nf = 0; nf < 2; nf++) {
            int g = wid * 2 + nf;
            uint2 ba = __ldg(WA + g * 256 + kg * 32 + lane);
            uint2 bq = __ldg(WQ + g * 256 + kg * 32 + lane);
#pragma unroll
            for (int mf = 0; mf < 4; mf++) {
                mma16h(acc_a[mf][nf], a[mf][0], a[mf][1], a[mf][2], a[mf][3], ba.x, ba.y);
                mma16h(acc_q[mf][nf], a[mf][0], a[mf][1], a[mf][2], a[mf][3], bq.x, bq.y);
            }
        }
    }

    // epilogue: P = (a + ab) * sigmoid(q + agb) -> fp16 staged in sP (pair-perm rows)
#pragma unroll
    for (int nf = 0; nf < 2; nf++) {
        int col = wid * 16 + nf * 8 + 2 * lc;
        float ba0 = __ldg(ab + col),  ba1 = __ldg(ab + col + 1);
        float bq0 = __ldg(agb + col), bq1 = __ldg(agb + col + 1);
#pragma unroll
        for (int mf = 0; mf < 4; mf++) {
            int r0 = p16(mf * 16 + lr), r1 = p16(mf * 16 + 8 + lr);
            sP[col * PH + r0]       = __float2half_rn((acc_a[mf][nf][0] + ba0) * sigmoidf_(acc_q[mf][nf][0] + bq0));
            sP[(col + 1) * PH + r0] = __float2half_rn((acc_a[mf][nf][1] + ba1) * sigmoidf_(acc_q[mf][nf][1] + bq1));
            sP[col * PH + r1]       = __float2half_rn((acc_a[mf][nf][2] + ba0) * sigmoidf_(acc_q[mf][nf][2] + bq0));
            sP[(col + 1) * PH + r1] = __float2half_rn((acc_a[mf][nf][3] + ba1) * sigmoidf_(acc_q[mf][nf][3] + bq1));
        }
    }
    __syncthreads();

    // coalesced uint4 store of fp16 a-tile: 128 cols x 64 halves
#pragma unroll
    for (int e = 0; e < 4; e++) {
        int idx = tid + 256 * e;           // 1024 uint4
        int c = idx >> 3, e8 = idx & 7;    // 8 uint4 per col
        uint4 v = *reinterpret_cast<const uint4*>(sP + c * PH + e8 * 8);
        *reinterpret_cast<uint4*>(g_at + (size_t)c * LL + m0 + e8 * 8) = v;
    }

    // ---- fp16 gate GEMM (sZ unmodified) ----
    float acc_g[4][2][4];
#pragma unroll
    for (int mf = 0; mf < 4; mf++)
#pragma unroll
        for (int nf = 0; nf < 2; nf++)
#pragma unroll
            for (int v = 0; v < 4; v++) acc_g[mf][nf][v] = 0.0f;

#pragma unroll
    for (int kg = 0; kg < 8; kg++) {
        int kb = kg * 8;
        uint32_t a[4][4];
#pragma unroll
        for (int mf = 0; mf < 4; mf++) {
            int row = mf * 16 + lr;
            uint2 lo = *reinterpret_cast<const uint2*>(sZw + row * PW + kb + 2 * lc);
            uint2 hi = *reinterpret_cast<const uint2*>(sZw + (row + 8) * PW + kb + 2 * lc);
            a[mf][0] = lo.x; a[mf][1] = hi.x; a[mf][2] = lo.y; a[mf][3] = hi.y;
        }
#pragma unroll
        for (int nf = 0; nf < 2; nf++) {
            int g = wid * 2 + nf;
            uint2 bg = __ldg(WG + g * 256 + kg * 32 + lane);
#pragma unroll
            for (int mf = 0; mf < 4; mf++)
                mma16h(acc_g[mf][nf], a[mf][0], a[mf][1], a[mf][2], a[mf][3], bg.x, bg.y);
        }
    }

    // gate stored frag-major fp16 (coalesced __half2)
#pragma unroll
    for (int nf = 0; nf < 2; nf++) {
        int col = wid * 16 + nf * 8 + 2 * lc;
        float b0v = __ldg(gb + col), b1v = __ldg(gb + col + 1);
#pragma unroll
        for (int mf = 0; mf < 4; mf++) {
            size_t row = m0 + mf * 16 + lr;
            size_t fi = gate_fi(row, col);
            GATE2[fi]      = __floats2half2_rn(sigmoidf_(acc_g[mf][nf][0] + b0v),
                                               sigmoidf_(acc_g[mf][nf][1] + b1v));
            GATE2[fi + 32] = __floats2half2_rn(sigmoidf_(acc_g[mf][nf][2] + b0v),
                                               sigmoidf_(acc_g[mf][nf][3] + b1v));
        }
    }
}

// ============================================================
// K2: fp16 SYRK per channel (m16n8k16, fp32 accum), cp.async
//     double-buffered, k-chunk 64. fp16 output, mirror staged
//     through smem for coalesced stores. 256 thr.
// ============================================================
__global__ void __launch_bounds__(256, 2)
syrk_mma() {
    extern __shared__ uint32_t sm[];   // 2 stages x (A + B), pitch PS words/row
    const int tid  = threadIdx.x;
    const int wid  = tid >> 5, lane = tid & 31;
    const int wm   = wid >> 1, wn = wid & 1;
    const int lr   = lane >> 2, lc = lane & 3;

    const int c = blockIdx.y;
    int rem = blockIdx.x, bi = 0, span = 4;
    while (rem >= span) { rem -= span; span--; bi++; }
    int bj = bi + rem;
    const int i0 = bi * 128, j0 = bj * 128;
    const bool diag = (bi == bj);

    const __half* __restrict__ Ag = g_at + (size_t)c * LL;
    __half* __restrict__ O = g_o + (size_t)c * LL;

    const int STG_SZ = 2 * 128 * PS;   // words per stage (A+B)

    auto load_chunk = [&](int kc, int buf) {
        uint32_t* sA = sm + buf * STG_SZ;
        uint32_t* sB = sA + 128 * PS;
#pragma unroll
        for (int e = 0; e < 4; e++) {
            int idx = tid + 256 * e;
            int r = idx >> 3, c8 = idx & 7;
            cpa16(sA + r * PS + c8 * 4, Ag + (size_t)(i0 + r) * 512 + kc * 64 + c8 * 8);
            if (!diag)
                cpa16(sB + r * PS + c8 * 4, Ag + (size_t)(j0 + r) * 512 + kc * 64 + c8 * 8);
        }
        cpa_commit();
    };

    float acc[2][8][4];
#pragma unroll
    for (int mf = 0; mf < 2; mf++)
#pragma unroll
        for (int nf = 0; nf < 8; nf++)
#pragma unroll
            for (int v = 0; v < 4; v++) acc[mf][nf][v] = 0.0f;

    load_chunk(0, 0);

    for (int kc = 0; kc < 8; kc++) {
        if (kc + 1 < 8) { load_chunk(kc + 1, (kc + 1) & 1); cpa_wait<1>(); }
        else            { cpa_wait<0>(); }
        __syncthreads();
        const uint32_t* sA = sm + (kc & 1) * STG_SZ;
        const uint32_t* sB = diag ? sA : sA + 128 * PS;
#pragma unroll
        for (int g = 0; g < 4; g++) {
            int kb = g * 8;
            uint32_t a[2][4];
#pragma unroll
            for (int mf = 0; mf < 2; mf++) {
                int row = wm * 32 + mf * 16 + lr;
                uint2 lo = *reinterpret_cast<const uint2*>(sA + row * PS + kb + 2 * lc);
                uint2 hi = *reinterpret_cast<const uint2*>(sA + (row + 8) * PS + kb + 2 * lc);
                a[mf][0] = lo.x; a[mf][1] = hi.x; a[mf][2] = lo.y; a[mf][3] = hi.y;
            }
#pragma unroll
            for (int nf = 0; nf < 8; nf++) {
                int col = wn * 64 + nf * 8 + lr;
                uint2 b = *reinterpret_cast<const uint2*>(sB + col * PS + kb + 2 * lc);
                mma16h(acc[0][nf], a[0][0], a[0][1], a[0][2], a[0][3], b.x, b.y);
                mma16h(acc[1][nf], a[1][0], a[1][1], a[1][2], a[1][3], b.x, b.y);
            }
        }
        __syncthreads();
    }

    // direct tile write (fp16 __half2)
#pragma unroll
    for (int mf = 0; mf < 2; mf++) {
#pragma unroll
        for (int nf = 0; nf < 8; nf++) {
            int rowi = i0 + wm * 32 + mf * 16 + lr;
            int colj = j0 + wn * 64 + nf * 8 + 2 * lc;
            *reinterpret_cast<__half2*>(O + (size_t)rowi * 512 + colj) =
                __floats2half2_rn(acc[mf][nf][0], acc[mf][nf][1]);
            *reinterpret_cast<__half2*>(O + (size_t)(rowi + 8) * 512 + colj) =
                __floats2half2_rn(acc[mf][nf][2], acc[mf][nf][3]);
        }
    }

    // mirror: stage transposed fp16 tile in smem, then coalesced uint4 stores
    if (!diag) {
        __half* st = reinterpret_cast<__half*>(sm);   // [col 128][row], pitch 136 halves
#pragma unroll
        for (int mf = 0; mf < 2; mf++) {
#pragma unroll
            for (int nf = 0; nf < 8; nf++) {
                int r  = wm * 32 + mf * 16 + lr;
                int cA = wn * 64 + nf * 8 + 2 * lc;
                st[cA * 136 + r]           = __float2half_rn(acc[mf][nf][0]);
                st[(cA + 1) * 136 + r]     = __float2half_rn(acc[mf][nf][1]);
                st[cA * 136 + r + 8]       = __float2half_rn(acc[mf][nf][2]);
                st[(cA + 1) * 136 + r + 8] = __float2half_rn(acc[mf][nf][3]);
            }
        }
        __syncthreads();
#pragma unroll
        for (int e = 0; e < 8; e++) {
            int idx = tid + 256 * e;        // 2048 uint4
            int col = idx >> 4, e8 = idx & 15;
            uint4 v = *reinterpret_cast<const uint4*>(st + col * 136 + e8 * 8);
            *reinterpret_cast<uint4*>(O + (size_t)(j0 + col) * 512 + i0 + e8 * 8) = v;
        }
    }
}

// ============================================================
// K3: fused gather (fp16 smem, cp.async) + channel-LN + fp16
//     projection + fp16 gating. smem 36.9 KB, 3 CTAs/SM.
// ============================================================
__global__ void __launch_bounds__(256, 3)
fusedC(const float* __restrict__ ong, const float* __restrict__ onb,
       const float* __restrict__ ob, float* __restrict__ out) {
    extern __shared__ uint32_t sm[];
    __half*   sOh = reinterpret_cast<__half*>(sm);  // [c 128][jj 64], pitch POH halves
    uint32_t* sTw = sm + 128 * (POH / 2);           // fp16 [jj 64][p16 c], pitch PW words
    __half*   sTh = reinterpret_cast<__half*>(sTw);
    __shared__ float ps[4][64], pq[4][64], mS[64], rS[64];

    const int tid = threadIdx.x;
    const int wid = tid >> 5, lane = tid & 31;
    const int wm = wid >> 2, wn = wid & 3;
    const int lr = lane >> 2, lc = lane & 3;
    const int i = blockIdx.y, j0 = blockIdx.x * 64;

    const uint2* WO = reinterpret_cast<const uint2*>(g_owh);
    const __half2* GATE2 = reinterpret_cast<const __half2*>(g_gate);

    // gather o tile [c][jj] fp16 via cp.async (deep MLP)
#pragma unroll
    for (int e = 0; e < 4; e++) {
        int idx = tid + 256 * e;       // 1024 x 16B
        int c = idx >> 3, j8 = idx & 7;
        cpa16(sOh + c * POH + j8 * 8, g_o + (size_t)c * LL + (size_t)i * 512 + j0 + j8 * 8);
    }
    cpa_commit();
    cpa_wait<0>();
    __syncthreads();

    // channel reduce (convert fp16 on the fly)
    {
        int col = tid & 63, qtr = tid >> 6;
        float s = 0.0f, q = 0.0f;
#pragma unroll 8
        for (int c = qtr * 32; c < qtr * 32 + 32; c++) {
            float v = __half2float(sOh[c * POH + col]);
            s += v; q += v * v;
        }
        ps[qtr][col] = s; pq[qtr][col] = q;
    }
    __syncthreads();
    if (tid < 64) {
        float ss = ps[0][tid] + ps[1][tid] + ps[2][tid] + ps[3][tid];
        float qq = pq[0][tid] + pq[1][tid] + pq[2][tid] + pq[3][tid];
        float mean = ss * (1.0f / 128.0f);
        float var  = qq * (1.0f / 128.0f) - mean * mean;
        mS[tid] = mean;
        rS[tid] = rsqrtf(var + 1e-5f);
    }
    __syncthreads();

    // normalize -> transposed + p16-permuted fp16 in sT
    {
        const int warp = wid;
#pragma unroll 8
        for (int e = 0; e < 32; e++) {
            int gidx = e * 8 + warp;
            int c = (gidx & 15) * 8 + (lane & 7);
            int jj = (gidx >> 4) * 4 + (lane >> 3);
            float v = (__half2float(sOh[c * POH + jj]) - mS[jj]) * rS[jj] * __ldg(ong + c) + __ldg(onb + c);
            sTh[jj * (2 * PW) + p16(c)] = __float2half_rn(v);
        }
    }
    __syncthreads();

    // fp16 GEMM: rows = jj, K = c, B frag-major L1
    float acc[2][4][4];
#pragma unroll
    for (int mf = 0; mf < 2; mf++)
#pragma unroll
        for (int nf = 0; nf < 4; nf++)
#pragma unroll
            for (int v = 0; v < 4; v++) acc[mf][nf][v] = 0.0f;

#pragma unroll
    for (int kg = 0; kg < 8; kg++) {
        int kb = kg * 8;
        uint32_t a[2][4];
#pragma unroll
        for (int mf = 0; mf < 2; mf++) {
            int row = wm * 32 + mf * 16 + lr;
            uint2 lo = *reinterpret_cast<const uint2*>(sTw + row * PW + kb + 2 * lc);
            uint2 hi = *reinterpret_cast<const uint2*>(sTw + (row + 8) * PW + kb + 2 * lc);
            a[mf][0] = lo.x; a[mf][1] = hi.x; a[mf][2] = lo.y; a[mf][3] = hi.y;
        }
#pragma unroll
        for (int nf = 0; nf < 4; nf++) {
            int g = wn * 4 + nf;
            uint2 b = __ldg(WO + g * 256 + kg * 32 + lane);
            mma16h(acc[0][nf], a[0][0], a[0][1], a[0][2], a[0][3], b.x, b.y);
            mma16h(acc[1][nf], a[1][0], a[1][1], a[1][2], a[1][3], b.x, b.y);
        }
    }
    __syncthreads();   // sOh + sT no longer needed; reuse whole smem as fp32 stage

    // epilogue: bias + fp16 gate (frag-major), stage fp32 into sR (base of smem)
    const size_t grow = (size_t)i * 512 + j0;
    float* sR = reinterpret_cast<float*>(sm);       // pitch PR floats, 64 rows
#pragma unroll
    for (int mf = 0; mf < 2; mf++) {
#pragma unroll
        for (int nf = 0; nf < 4; nf++) {
            int jj = wm * 32 + mf * 16 + lr;
            int col = wn * 32 + nf * 8 + 2 * lc;
            float b0v = __ldg(ob + col), b1v = __ldg(ob + col + 1);
            size_t fi = gate_fi(grow + jj, col);
            float2 gt0 = __half22float2(GATE2[fi]);
            float2 gt1 = __half22float2(GATE2[fi + 32]);
            *reinterpret_cast<float2*>(sR + jj * PR + col) =
                make_float2((acc[mf][nf][0] + b0v) * gt0.x, (acc[mf][nf][1] + b1v) * gt0.y);
            *reinterpret_cast<float2*>(sR + (jj + 8) * PR + col) =
                make_float2((acc[mf][nf][2] + b0v) * gt1.x, (acc[mf][nf][3] + b1v) * gt1.y);
        }
    }
    __syncthreads();

    // coalesced output store
#pragma unroll 4
    for (int e = 0; e < 16; e++) {
        int idx = tid + 256 * e;
        int jj = idx >> 6, c2 = idx & 63;
        float2 v = *reinterpret_cast<const float2*>(sR + jj * PR + 2 * c2);
        *reinterpret_cast<float2*>(out + (grow + jj) * 128 + 2 * c2) = v;
    }
}

// ============================================================
// launch
// ============================================================
extern "C" void kernel_launch(void* const* d_in, const int* in_sizes, int n_in,
                              void* d_out, int out_size) {
    const float* z      = (const float*)d_in[0];
    const float* norm_g = (const float*)d_in[1];
    const float* norm_b = (const float*)d_in[2];
    const float* a_w    = (const float*)d_in[3];
    const float* a_b    = (const float*)d_in[4];
    const float* ag_w   = (const float*)d_in[5];
    const float* ag_b   = (const float*)d_in[6];
    const float* onorm_g= (const float*)d_in[7];
    const float* onorm_b= (const float*)d_in[8];
    const float* o_w    = (const float*)d_in[9];
    const float* o_b    = (const float*)d_in[10];
    const float* g_wp   = (const float*)d_in[11];
    const float* g_bp   = (const float*)d_in[12];
    float* out = (float*)d_out;

    const int SMA = 64 * PW * 4 + 128 * PH * 2;      // 36.9 KB
    const int SMS = 2 * 2 * 128 * PS * 4;            // 81.9 KB
    const int SMC = (128 * (POH / 2) + 64 * PW) * 4; // 36.9 KB (>= 64*PR*4 = 34.8 KB stage)

    static bool attr_done = false;
    if (!attr_done) {
        cudaFuncSetAttribute(fusedA,   cudaFuncAttributeMaxDynamicSharedMemorySize, SMA);
        cudaFuncSetAttribute(syrk_mma, cudaFuncAttributeMaxDynamicSharedMemorySize, SMS);
        cudaFuncSetAttribute(fusedC,   cudaFuncAttributeMaxDynamicSharedMemorySize, SMC);
        attr_done = true;
    }

    prep_w<<<32, 512>>>(a_w, ag_w, g_wp, o_w);
    fusedA<<<LL / 64, 256, SMA>>>(z, norm_g, norm_b, a_b, ag_b, g_bp);
    syrk_mma<<<dim3(10, 128), 256, SMS>>>();
    fusedC<<<dim3(8, L), 256, SMC>>>(onorm_g, onorm_b, o_b, out);
}